// round 2
// baseline (speedup 1.0000x reference)
#include <cuda_runtime.h>
#include <math.h>

#define Bc 4
#define C 256
#define Tn 4096
#define LATENT 128
#define TT 32
#define KC 8
#define NENC 40
#define NDEC 10

// ---------------- scratch ----------------
__device__ float g_h[2][Bc * C * Tn];     // double-buffered residual stream
__device__ float g_skip[Bc * C * Tn];     // skip sum
__device__ float g_pooled[Bc * C];
__device__ float g_z[Bc * LATENT];

// ---------------- encoder input conv (1->C, k=2) + skip zero ----------------
__global__ void enc_in_kernel(const float* __restrict__ x,
                              const float* __restrict__ W,
                              const float* __restrict__ bias) {
    int idx = blockIdx.x * 256 + threadIdx.x;      // [b][c][t]
    int t = idx & (Tn - 1);
    int c = (idx >> 12) & (C - 1);
    int b = idx >> 20;
    float xv = x[b * Tn + t];
    float xp = (t > 0) ? x[b * Tn + t - 1] : 0.f;
    g_h[0][idx] = W[c * 2] * xp + W[c * 2 + 1] * xv + bias[c];
    g_skip[idx] = 0.f;
}

// ---------------- gated residual block ----------------
// grid (Tn/TT, Bc), 256 threads. Dynamic smem:
//   sh_prev [C][TT]  (reused as sh_out in pass 2)
//   sh_cur  [C][TT]
//   sh_a    [2*KC*C]*2  (weight staging)
#define SMEM_FLOATS (2 * C * TT + 2 * 2 * KC * C)
#define SMEM_BYTES (SMEM_FLOATS * 4)

__global__ void __launch_bounds__(256, 1)
gated_block_kernel(int src,
                   const float* __restrict__ Wf, const float* __restrict__ bf,
                   const float* __restrict__ Wg, const float* __restrict__ bg,
                   const float* __restrict__ Wr, const float* __restrict__ br,
                   const float* __restrict__ Ws, const float* __restrict__ bs,
                   int dil) {
    extern __shared__ float sm[];
    float* sh_prev = sm;                    // [C][TT]
    float* sh_cur  = sm + C * TT;           // [C][TT]
    float* sh_af   = sm + 2 * C * TT;       // [2*KC][C]
    float* sh_ag   = sh_af + 2 * KC * C;    // [2*KC][C]

    const int b = blockIdx.y;
    const int t0 = blockIdx.x * TT;
    const int tid = threadIdx.x;
    const float* __restrict__ h_in = g_h[src] + b * C * Tn;
    float* __restrict__ h_out = g_h[src ^ 1] + b * C * Tn;
    float* __restrict__ skip = g_skip + b * C * Tn;

    // load current + dilated-past tiles (coalesced along t)
    #pragma unroll
    for (int i = tid; i < C * TT; i += 256) {
        int c = i >> 5, n = i & 31;
        sh_cur[i] = h_in[c * Tn + t0 + n];
        int tp = t0 + n - dil;
        sh_prev[i] = (tp >= 0) ? h_in[c * Tn + tp] : 0.f;
    }

    const int tx = tid & 7;     // n-group
    const int ty = tid >> 3;    // m-group
    const int n0 = tx * 4, m0 = ty * 8;

    // ---------------- pass 1: f and g convs (K = 2*C via 2 taps) ----------------
    float accf[8][4], accg[8][4];
    #pragma unroll
    for (int m = 0; m < 8; ++m) {
        float vf = bf[m0 + m], vg = bg[m0 + m];
        #pragma unroll
        for (int n = 0; n < 4; ++n) { accf[m][n] = vf; accg[m][n] = vg; }
    }

    for (int kc = 0; kc < C; kc += KC) {
        __syncthreads();   // also covers tile-load on first iter
        // stage weights: thread tid == output channel o, 16 contiguous floats each
        {
            const float4* pf = (const float4*)(Wf + tid * (2 * C) + kc * 2);
            const float4* pg = (const float4*)(Wg + tid * (2 * C) + kc * 2);
            #pragma unroll
            for (int j4 = 0; j4 < 4; ++j4) {
                float4 vf = __ldg(pf + j4);
                float4 vg = __ldg(pg + j4);
                int j = j4 * 4;
                sh_af[(j + 0) * C + tid] = vf.x;
                sh_af[(j + 1) * C + tid] = vf.y;
                sh_af[(j + 2) * C + tid] = vf.z;
                sh_af[(j + 3) * C + tid] = vf.w;
                sh_ag[(j + 0) * C + tid] = vg.x;
                sh_ag[(j + 1) * C + tid] = vg.y;
                sh_ag[(j + 2) * C + tid] = vg.z;
                sh_ag[(j + 3) * C + tid] = vg.w;
            }
        }
        __syncthreads();
        #pragma unroll
        for (int k = 0; k < KC; ++k) {
            float bp[4], bc[4];
            *(float4*)bp = *(const float4*)&sh_prev[(kc + k) * TT + n0];
            *(float4*)bc = *(const float4*)&sh_cur[(kc + k) * TT + n0];
            float af0[8], af1[8], ag0[8], ag1[8];
            *(float4*)&af0[0] = *(const float4*)&sh_af[(2 * k + 0) * C + m0];
            *(float4*)&af0[4] = *(const float4*)&sh_af[(2 * k + 0) * C + m0 + 4];
            *(float4*)&af1[0] = *(const float4*)&sh_af[(2 * k + 1) * C + m0];
            *(float4*)&af1[4] = *(const float4*)&sh_af[(2 * k + 1) * C + m0 + 4];
            *(float4*)&ag0[0] = *(const float4*)&sh_ag[(2 * k + 0) * C + m0];
            *(float4*)&ag0[4] = *(const float4*)&sh_ag[(2 * k + 0) * C + m0 + 4];
            *(float4*)&ag1[0] = *(const float4*)&sh_ag[(2 * k + 1) * C + m0];
            *(float4*)&ag1[4] = *(const float4*)&sh_ag[(2 * k + 1) * C + m0 + 4];
            #pragma unroll
            for (int m = 0; m < 8; ++m)
                #pragma unroll
                for (int n = 0; n < 4; ++n) {
                    accf[m][n] += af0[m] * bp[n];
                    accf[m][n] += af1[m] * bc[n];
                    accg[m][n] += ag0[m] * bp[n];
                    accg[m][n] += ag1[m] * bc[n];
                }
        }
    }

    // gated nonlinearity -> smem (reuse sh_prev)
    __syncthreads();      // everyone done reading sh_prev
    float* sh_out = sh_prev;
    #pragma unroll
    for (int m = 0; m < 8; ++m)
        #pragma unroll
        for (int n = 0; n < 4; ++n) {
            float f = tanhf(accf[m][n]);
            float gg = 1.f / (1.f + expf(-accg[m][n]));
            sh_out[(m0 + m) * TT + n0 + n] = f * gg;
        }

    // ---------------- pass 2: res & skip 1x1 projections ----------------
    float accr[8][4], accs[8][4];
    #pragma unroll
    for (int m = 0; m < 8; ++m) {
        float rb = br[m0 + m], sb = bs[m0 + m];
        #pragma unroll
        for (int n = 0; n < 4; ++n) {
            accr[m][n] = rb + sh_cur[(m0 + m) * TT + n0 + n];   // + residual h
            accs[m][n] = sb;
        }
    }
    float* sh_ar = sh_af;               // [KC][C]
    float* sh_as = sh_af + KC * C;      // [KC][C]
    for (int kc = 0; kc < C; kc += KC) {
        __syncthreads();
        {
            const float4* pr = (const float4*)(Wr + tid * C + kc);
            const float4* ps = (const float4*)(Ws + tid * C + kc);
            #pragma unroll
            for (int j4 = 0; j4 < 2; ++j4) {
                float4 vr = __ldg(pr + j4);
                float4 vs = __ldg(ps + j4);
                int j = j4 * 4;
                sh_ar[(j + 0) * C + tid] = vr.x;
                sh_ar[(j + 1) * C + tid] = vr.y;
                sh_ar[(j + 2) * C + tid] = vr.z;
                sh_ar[(j + 3) * C + tid] = vr.w;
                sh_as[(j + 0) * C + tid] = vs.x;
                sh_as[(j + 1) * C + tid] = vs.y;
                sh_as[(j + 2) * C + tid] = vs.z;
                sh_as[(j + 3) * C + tid] = vs.w;
            }
        }
        __syncthreads();
        #pragma unroll
        for (int k = 0; k < KC; ++k) {
            float bo[4];
            *(float4*)bo = *(const float4*)&sh_out[(kc + k) * TT + n0];
            float ar[8], as[8];
            *(float4*)&ar[0] = *(const float4*)&sh_ar[k * C + m0];
            *(float4*)&ar[4] = *(const float4*)&sh_ar[k * C + m0 + 4];
            *(float4*)&as[0] = *(const float4*)&sh_as[k * C + m0];
            *(float4*)&as[4] = *(const float4*)&sh_as[k * C + m0 + 4];
            #pragma unroll
            for (int m = 0; m < 8; ++m)
                #pragma unroll
                for (int n = 0; n < 4; ++n) {
                    accr[m][n] += ar[m] * bo[n];
                    accs[m][n] += as[m] * bo[n];
                }
        }
    }

    // epilogue: write residual stream, accumulate skip (vectorized)
    #pragma unroll
    for (int m = 0; m < 8; ++m) {
        int gi = (m0 + m) * Tn + t0 + n0;
        float4 r;
        r.x = accr[m][0]; r.y = accr[m][1]; r.z = accr[m][2]; r.w = accr[m][3];
        *(float4*)&h_out[gi] = r;
        float4 so = *(const float4*)&skip[gi];
        so.x += accs[m][0]; so.y += accs[m][1];
        so.z += accs[m][2]; so.w += accs[m][3];
        *(float4*)&skip[gi] = so;
    }
}

// ---------------- mean pool over time ----------------
__global__ void pool_kernel() {
    __shared__ float red[256];
    int row = blockIdx.x;  // b*C + c
    const float* p = g_skip + row * Tn;
    float s = 0.f;
    for (int t = threadIdx.x; t < Tn; t += 256) s += p[t];
    red[threadIdx.x] = s;
    __syncthreads();
    for (int off = 128; off; off >>= 1) {
        if (threadIdx.x < off) red[threadIdx.x] += red[threadIdx.x + off];
        __syncthreads();
    }
    if (threadIdx.x == 0) g_pooled[row] = red[0] * (1.f / Tn);
}

// ---------------- mu / logvar / reparameterize ----------------
__global__ void fc_kernel(const float* __restrict__ muW, const float* __restrict__ mub,
                          const float* __restrict__ lvW, const float* __restrict__ lvb,
                          const float* __restrict__ eps, float* __restrict__ out) {
    int b = blockIdx.x, l = threadIdx.x;   // 128 threads
    const float* p = g_pooled + b * C;
    float m0 = mub[l], m1 = 0.f, v0 = lvb[l], v1 = 0.f;
    const float* wm = muW + l * C;
    const float* wv = lvW + l * C;
    for (int c = 0; c < C; c += 2) {
        m0 += wm[c] * p[c];     m1 += wm[c + 1] * p[c + 1];
        v0 += wv[c] * p[c];     v1 += wv[c + 1] * p[c + 1];
    }
    float mu = m0 + m1, lv = v0 + v1;
    out[4 + b * LATENT + l] = mu;
    out[4 + Bc * LATENT + b * LATENT + l] = lv;
    g_z[b * LATENT + l] = mu + eps[b * LATENT + l] * expf(0.5f * lv);
}

// ---------------- decoder (T=1: only tap 1 of each k=2 conv contributes) ----------------
__global__ void dec_kernel(const float* __restrict__ inW, const float* __restrict__ inb,
                           const float* __restrict__ Wf, const float* __restrict__ bf,
                           const float* __restrict__ Wg, const float* __restrict__ bg,
                           const float* __restrict__ Wr, const float* __restrict__ br,
                           const float* __restrict__ outW, const float* __restrict__ outb,
                           float* __restrict__ out) {
    __shared__ float h2[C], fg[C], red[C];
    int b = blockIdx.x, c = threadIdx.x;   // 256 threads
    {
        float s = inb[c];
        const float* w = inW + c * LATENT;
        const float* zz = g_z + b * LATENT;
        for (int l = 0; l < LATENT; ++l) s += w[l] * zz[l];
        h2[c] = s;
    }
    __syncthreads();
    for (int i = 0; i < NDEC; ++i) {
        const float* wf = Wf + (size_t)(i * C + c) * C * 2;
        const float* wg = Wg + (size_t)(i * C + c) * C * 2;
        float f0 = bf[i * C + c], f1 = 0.f, g0 = bg[i * C + c], g1 = 0.f;
        for (int cc = 0; cc < C; cc += 2) {
            float h0 = h2[cc], h1 = h2[cc + 1];
            f0 += wf[cc * 2 + 1] * h0;  f1 += wf[cc * 2 + 3] * h1;
            g0 += wg[cc * 2 + 1] * h0;  g1 += wg[cc * 2 + 3] * h1;
        }
        float fv = f0 + f1, gv = g0 + g1;
        fg[c] = tanhf(fv) * (1.f / (1.f + expf(-gv)));
        __syncthreads();
        const float* wr = Wr + (size_t)(i * C + c) * C;
        float r0 = br[i * C + c], r1 = 0.f;
        for (int cc = 0; cc < C; cc += 2) {
            r0 += wr[cc] * fg[cc];
            r1 += wr[cc + 1] * fg[cc + 1];
        }
        h2[c] += r0 + r1;
        __syncthreads();
    }
    red[c] = outW[c] * h2[c];
    __syncthreads();
    for (int off = 128; off; off >>= 1) {
        if (c < off) red[c] += red[c + off];
        __syncthreads();
    }
    if (c == 0) out[b] = red[0] + outb[0];
}

// ---------------- host ----------------
extern "C" void kernel_launch(void* const* d_in, const int* in_sizes, int n_in,
                              void* d_out, int out_size) {
    const float* x        = (const float*)d_in[0];
    const float* eps      = (const float*)d_in[1];
    const float* enc_in_W = (const float*)d_in[2];
    const float* enc_in_b = (const float*)d_in[3];
    const float* enc_Wf   = (const float*)d_in[4];
    const float* enc_bf   = (const float*)d_in[5];
    const float* enc_Wg   = (const float*)d_in[6];
    const float* enc_bg   = (const float*)d_in[7];
    const float* enc_Wr   = (const float*)d_in[8];
    const float* enc_br   = (const float*)d_in[9];
    const float* enc_Ws   = (const float*)d_in[10];
    const float* enc_bs   = (const float*)d_in[11];
    const float* fc_mu_W  = (const float*)d_in[12];
    const float* fc_mu_b  = (const float*)d_in[13];
    const float* fc_lv_W  = (const float*)d_in[14];
    const float* fc_lv_b  = (const float*)d_in[15];
    const float* dec_in_W = (const float*)d_in[16];
    const float* dec_in_b = (const float*)d_in[17];
    const float* dec_Wf   = (const float*)d_in[18];
    const float* dec_bf   = (const float*)d_in[19];
    const float* dec_Wg   = (const float*)d_in[20];
    const float* dec_bg   = (const float*)d_in[21];
    const float* dec_Wr   = (const float*)d_in[22];
    const float* dec_br   = (const float*)d_in[23];
    const float* out_W    = (const float*)d_in[24];
    const float* out_b    = (const float*)d_in[25];
    float* out = (float*)d_out;

    cudaFuncSetAttribute(gated_block_kernel,
                         cudaFuncAttributeMaxDynamicSharedMemorySize, SMEM_BYTES);

    enc_in_kernel<<<(Bc * C * Tn) / 256, 256>>>(x, enc_in_W, enc_in_b);

    int src = 0;
    for (int i = 0; i < NENC; ++i) {
        int dil = 1 << (i % 10);
        gated_block_kernel<<<dim3(Tn / TT, Bc), 256, SMEM_BYTES>>>(
            src,
            enc_Wf + (size_t)i * C * C * 2, enc_bf + i * C,
            enc_Wg + (size_t)i * C * C * 2, enc_bg + i * C,
            enc_Wr + (size_t)i * C * C,     enc_br + i * C,
            enc_Ws + (size_t)i * C * C,     enc_bs + i * C,
            dil);
        src ^= 1;
    }

    pool_kernel<<<Bc * C, 256>>>();
    fc_kernel<<<Bc, LATENT>>>(fc_mu_W, fc_mu_b, fc_lv_W, fc_lv_b, eps, out);
    dec_kernel<<<Bc, C>>>(dec_in_W, dec_in_b, dec_Wf, dec_bf, dec_Wg, dec_bg,
                          dec_Wr, dec_br, out_W, out_b, out);
}

// round 3
// speedup vs baseline: 1.0003x; 1.0003x over previous
#include <cuda_runtime.h>
#include <math.h>

#define Bc 4
#define C 256
#define Tn 4096
#define LATENT 128
#define TT 32
#define KC 8
#define NENC 40
#define NDEC 10

// ---------------- scratch ----------------
__device__ float g_h[2][Bc * C * Tn];     // double-buffered residual stream
__device__ float g_skip[Bc * C * Tn];     // skip sum
__device__ float g_pooled[Bc * C];
__device__ float g_z[Bc * LATENT];

// ---------------- encoder input conv (1->C, k=2) + skip zero ----------------
__global__ void enc_in_kernel(const float* __restrict__ x,
                              const float* __restrict__ W,
                              const float* __restrict__ bias) {
    int idx = blockIdx.x * 256 + threadIdx.x;      // [b][c][t]
    int t = idx & (Tn - 1);
    int c = (idx >> 12) & (C - 1);
    int b = idx >> 20;
    float xv = x[b * Tn + t];
    float xp = (t > 0) ? x[b * Tn + t - 1] : 0.f;
    g_h[0][idx] = W[c * 2] * xp + W[c * 2 + 1] * xv + bias[c];
    g_skip[idx] = 0.f;
}

// ---------------- gated residual block ----------------
// grid (Tn/TT, Bc), 256 threads. Dynamic smem:
//   sh_prev [C][TT]  (reused as sh_out in pass 2)
//   sh_cur  [C][TT]
//   sh_a    [2*KC*C]*2  (weight staging)
#define SMEM_FLOATS (2 * C * TT + 2 * 2 * KC * C)
#define SMEM_BYTES (SMEM_FLOATS * 4)

__global__ void __launch_bounds__(256, 1)
gated_block_kernel(int src,
                   const float* __restrict__ Wf, const float* __restrict__ bf,
                   const float* __restrict__ Wg, const float* __restrict__ bg,
                   const float* __restrict__ Wr, const float* __restrict__ br,
                   const float* __restrict__ Ws, const float* __restrict__ bs,
                   int dil) {
    extern __shared__ float sm[];
    float* sh_prev = sm;                    // [C][TT]
    float* sh_cur  = sm + C * TT;           // [C][TT]
    float* sh_af   = sm + 2 * C * TT;       // [2*KC][C]
    float* sh_ag   = sh_af + 2 * KC * C;    // [2*KC][C]

    const int b = blockIdx.y;
    const int t0 = blockIdx.x * TT;
    const int tid = threadIdx.x;
    const float* __restrict__ h_in = g_h[src] + b * C * Tn;
    float* __restrict__ h_out = g_h[src ^ 1] + b * C * Tn;
    float* __restrict__ skip = g_skip + b * C * Tn;

    // load current + dilated-past tiles (coalesced along t)
    #pragma unroll
    for (int i = tid; i < C * TT; i += 256) {
        int c = i >> 5, n = i & 31;
        sh_cur[i] = h_in[c * Tn + t0 + n];
        int tp = t0 + n - dil;
        sh_prev[i] = (tp >= 0) ? h_in[c * Tn + tp] : 0.f;
    }

    const int tx = tid & 7;     // n-group
    const int ty = tid >> 3;    // m-group
    const int n0 = tx * 4, m0 = ty * 8;

    // ---------------- pass 1: f and g convs (K = 2*C via 2 taps) ----------------
    float accf[8][4], accg[8][4];
    #pragma unroll
    for (int m = 0; m < 8; ++m) {
        float vf = bf[m0 + m], vg = bg[m0 + m];
        #pragma unroll
        for (int n = 0; n < 4; ++n) { accf[m][n] = vf; accg[m][n] = vg; }
    }

    for (int kc = 0; kc < C; kc += KC) {
        __syncthreads();   // also covers tile-load on first iter
        // stage weights: thread tid == output channel o, 16 contiguous floats each
        {
            const float4* pf = (const float4*)(Wf + tid * (2 * C) + kc * 2);
            const float4* pg = (const float4*)(Wg + tid * (2 * C) + kc * 2);
            #pragma unroll
            for (int j4 = 0; j4 < 4; ++j4) {
                float4 vf = __ldg(pf + j4);
                float4 vg = __ldg(pg + j4);
                int j = j4 * 4;
                sh_af[(j + 0) * C + tid] = vf.x;
                sh_af[(j + 1) * C + tid] = vf.y;
                sh_af[(j + 2) * C + tid] = vf.z;
                sh_af[(j + 3) * C + tid] = vf.w;
                sh_ag[(j + 0) * C + tid] = vg.x;
                sh_ag[(j + 1) * C + tid] = vg.y;
                sh_ag[(j + 2) * C + tid] = vg.z;
                sh_ag[(j + 3) * C + tid] = vg.w;
            }
        }
        __syncthreads();
        #pragma unroll
        for (int k = 0; k < KC; ++k) {
            float bp[4], bc[4];
            *(float4*)bp = *(const float4*)&sh_prev[(kc + k) * TT + n0];
            *(float4*)bc = *(const float4*)&sh_cur[(kc + k) * TT + n0];
            float af0[8], af1[8], ag0[8], ag1[8];
            *(float4*)&af0[0] = *(const float4*)&sh_af[(2 * k + 0) * C + m0];
            *(float4*)&af0[4] = *(const float4*)&sh_af[(2 * k + 0) * C + m0 + 4];
            *(float4*)&af1[0] = *(const float4*)&sh_af[(2 * k + 1) * C + m0];
            *(float4*)&af1[4] = *(const float4*)&sh_af[(2 * k + 1) * C + m0 + 4];
            *(float4*)&ag0[0] = *(const float4*)&sh_ag[(2 * k + 0) * C + m0];
            *(float4*)&ag0[4] = *(const float4*)&sh_ag[(2 * k + 0) * C + m0 + 4];
            *(float4*)&ag1[0] = *(const float4*)&sh_ag[(2 * k + 1) * C + m0];
            *(float4*)&ag1[4] = *(const float4*)&sh_ag[(2 * k + 1) * C + m0 + 4];
            #pragma unroll
            for (int m = 0; m < 8; ++m)
                #pragma unroll
                for (int n = 0; n < 4; ++n) {
                    accf[m][n] += af0[m] * bp[n];
                    accf[m][n] += af1[m] * bc[n];
                    accg[m][n] += ag0[m] * bp[n];
                    accg[m][n] += ag1[m] * bc[n];
                }
        }
    }

    // gated nonlinearity -> smem (reuse sh_prev)
    __syncthreads();      // everyone done reading sh_prev
    float* sh_out = sh_prev;
    #pragma unroll
    for (int m = 0; m < 8; ++m)
        #pragma unroll
        for (int n = 0; n < 4; ++n) {
            float f = tanhf(accf[m][n]);
            float gg = 1.f / (1.f + expf(-accg[m][n]));
            sh_out[(m0 + m) * TT + n0 + n] = f * gg;
        }

    // ---------------- pass 2: res & skip 1x1 projections ----------------
    float accr[8][4], accs[8][4];
    #pragma unroll
    for (int m = 0; m < 8; ++m) {
        float rb = br[m0 + m], sb = bs[m0 + m];
        #pragma unroll
        for (int n = 0; n < 4; ++n) {
            accr[m][n] = rb + sh_cur[(m0 + m) * TT + n0 + n];   // + residual h
            accs[m][n] = sb;
        }
    }
    float* sh_ar = sh_af;               // [KC][C]
    float* sh_as = sh_af + KC * C;      // [KC][C]
    for (int kc = 0; kc < C; kc += KC) {
        __syncthreads();
        {
            const float4* pr = (const float4*)(Wr + tid * C + kc);
            const float4* ps = (const float4*)(Ws + tid * C + kc);
            #pragma unroll
            for (int j4 = 0; j4 < 2; ++j4) {
                float4 vr = __ldg(pr + j4);
                float4 vs = __ldg(ps + j4);
                int j = j4 * 4;
                sh_ar[(j + 0) * C + tid] = vr.x;
                sh_ar[(j + 1) * C + tid] = vr.y;
                sh_ar[(j + 2) * C + tid] = vr.z;
                sh_ar[(j + 3) * C + tid] = vr.w;
                sh_as[(j + 0) * C + tid] = vs.x;
                sh_as[(j + 1) * C + tid] = vs.y;
                sh_as[(j + 2) * C + tid] = vs.z;
                sh_as[(j + 3) * C + tid] = vs.w;
            }
        }
        __syncthreads();
        #pragma unroll
        for (int k = 0; k < KC; ++k) {
            float bo[4];
            *(float4*)bo = *(const float4*)&sh_out[(kc + k) * TT + n0];
            float ar[8], as[8];
            *(float4*)&ar[0] = *(const float4*)&sh_ar[k * C + m0];
            *(float4*)&ar[4] = *(const float4*)&sh_ar[k * C + m0 + 4];
            *(float4*)&as[0] = *(const float4*)&sh_as[k * C + m0];
            *(float4*)&as[4] = *(const float4*)&sh_as[k * C + m0 + 4];
            #pragma unroll
            for (int m = 0; m < 8; ++m)
                #pragma unroll
                for (int n = 0; n < 4; ++n) {
                    accr[m][n] += ar[m] * bo[n];
                    accs[m][n] += as[m] * bo[n];
                }
        }
    }

    // epilogue: write residual stream, accumulate skip (vectorized)
    #pragma unroll
    for (int m = 0; m < 8; ++m) {
        int gi = (m0 + m) * Tn + t0 + n0;
        float4 r;
        r.x = accr[m][0]; r.y = accr[m][1]; r.z = accr[m][2]; r.w = accr[m][3];
        *(float4*)&h_out[gi] = r;
        float4 so = *(const float4*)&skip[gi];
        so.x += accs[m][0]; so.y += accs[m][1];
        so.z += accs[m][2]; so.w += accs[m][3];
        *(float4*)&skip[gi] = so;
    }
}

// ---------------- mean pool over time ----------------
__global__ void pool_kernel() {
    __shared__ float red[256];
    int row = blockIdx.x;  // b*C + c
    const float* p = g_skip + row * Tn;
    float s = 0.f;
    for (int t = threadIdx.x; t < Tn; t += 256) s += p[t];
    red[threadIdx.x] = s;
    __syncthreads();
    for (int off = 128; off; off >>= 1) {
        if (threadIdx.x < off) red[threadIdx.x] += red[threadIdx.x + off];
        __syncthreads();
    }
    if (threadIdx.x == 0) g_pooled[row] = red[0] * (1.f / Tn);
}

// ---------------- mu / logvar / reparameterize ----------------
__global__ void fc_kernel(const float* __restrict__ muW, const float* __restrict__ mub,
                          const float* __restrict__ lvW, const float* __restrict__ lvb,
                          const float* __restrict__ eps, float* __restrict__ out) {
    int b = blockIdx.x, l = threadIdx.x;   // 128 threads
    const float* p = g_pooled + b * C;
    float m0 = mub[l], m1 = 0.f, v0 = lvb[l], v1 = 0.f;
    const float* wm = muW + l * C;
    const float* wv = lvW + l * C;
    for (int c = 0; c < C; c += 2) {
        m0 += wm[c] * p[c];     m1 += wm[c + 1] * p[c + 1];
        v0 += wv[c] * p[c];     v1 += wv[c + 1] * p[c + 1];
    }
    float mu = m0 + m1, lv = v0 + v1;
    out[4 + b * LATENT + l] = mu;
    out[4 + Bc * LATENT + b * LATENT + l] = lv;
    g_z[b * LATENT + l] = mu + eps[b * LATENT + l] * expf(0.5f * lv);
}

// ---------------- decoder (T=1: only tap 1 of each k=2 conv contributes) ----------------
__global__ void dec_kernel(const float* __restrict__ inW, const float* __restrict__ inb,
                           const float* __restrict__ Wf, const float* __restrict__ bf,
                           const float* __restrict__ Wg, const float* __restrict__ bg,
                           const float* __restrict__ Wr, const float* __restrict__ br,
                           const float* __restrict__ outW, const float* __restrict__ outb,
                           float* __restrict__ out) {
    __shared__ float h2[C], fg[C], red[C];
    int b = blockIdx.x, c = threadIdx.x;   // 256 threads
    {
        float s = inb[c];
        const float* w = inW + c * LATENT;
        const float* zz = g_z + b * LATENT;
        for (int l = 0; l < LATENT; ++l) s += w[l] * zz[l];
        h2[c] = s;
    }
    __syncthreads();
    for (int i = 0; i < NDEC; ++i) {
        const float* wf = Wf + (size_t)(i * C + c) * C * 2;
        const float* wg = Wg + (size_t)(i * C + c) * C * 2;
        float f0 = bf[i * C + c], f1 = 0.f, g0 = bg[i * C + c], g1 = 0.f;
        for (int cc = 0; cc < C; cc += 2) {
            float h0 = h2[cc], h1 = h2[cc + 1];
            f0 += wf[cc * 2 + 1] * h0;  f1 += wf[cc * 2 + 3] * h1;
            g0 += wg[cc * 2 + 1] * h0;  g1 += wg[cc * 2 + 3] * h1;
        }
        float fv = f0 + f1, gv = g0 + g1;
        fg[c] = tanhf(fv) * (1.f / (1.f + expf(-gv)));
        __syncthreads();
        const float* wr = Wr + (size_t)(i * C + c) * C;
        float r0 = br[i * C + c], r1 = 0.f;
        for (int cc = 0; cc < C; cc += 2) {
            r0 += wr[cc] * fg[cc];
            r1 += wr[cc + 1] * fg[cc + 1];
        }
        h2[c] += r0 + r1;
        __syncthreads();
    }
    red[c] = outW[c] * h2[c];
    __syncthreads();
    for (int off = 128; off; off >>= 1) {
        if (c < off) red[c] += red[c + off];
        __syncthreads();
    }
    if (c == 0) out[b] = red[0] + outb[0];
}

// ---------------- host ----------------
extern "C" void kernel_launch(void* const* d_in, const int* in_sizes, int n_in,
                              void* d_out, int out_size) {
    const float* x        = (const float*)d_in[0];
    const float* eps      = (const float*)d_in[1];
    const float* enc_in_W = (const float*)d_in[2];
    const float* enc_in_b = (const float*)d_in[3];
    const float* enc_Wf   = (const float*)d_in[4];
    const float* enc_bf   = (const float*)d_in[5];
    const float* enc_Wg   = (const float*)d_in[6];
    const float* enc_bg   = (const float*)d_in[7];
    const float* enc_Wr   = (const float*)d_in[8];
    const float* enc_br   = (const float*)d_in[9];
    const float* enc_Ws   = (const float*)d_in[10];
    const float* enc_bs   = (const float*)d_in[11];
    const float* fc_mu_W  = (const float*)d_in[12];
    const float* fc_mu_b  = (const float*)d_in[13];
    const float* fc_lv_W  = (const float*)d_in[14];
    const float* fc_lv_b  = (const float*)d_in[15];
    const float* dec_in_W = (const float*)d_in[16];
    const float* dec_in_b = (const float*)d_in[17];
    const float* dec_Wf   = (const float*)d_in[18];
    const float* dec_bf   = (const float*)d_in[19];
    const float* dec_Wg   = (const float*)d_in[20];
    const float* dec_bg   = (const float*)d_in[21];
    const float* dec_Wr   = (const float*)d_in[22];
    const float* dec_br   = (const float*)d_in[23];
    const float* out_W    = (const float*)d_in[24];
    const float* out_b    = (const float*)d_in[25];
    float* out = (float*)d_out;

    cudaFuncSetAttribute(gated_block_kernel,
                         cudaFuncAttributeMaxDynamicSharedMemorySize, SMEM_BYTES);

    enc_in_kernel<<<(Bc * C * Tn) / 256, 256>>>(x, enc_in_W, enc_in_b);

    int src = 0;
    for (int i = 0; i < NENC; ++i) {
        int dil = 1 << (i % 10);
        gated_block_kernel<<<dim3(Tn / TT, Bc), 256, SMEM_BYTES>>>(
            src,
            enc_Wf + (size_t)i * C * C * 2, enc_bf + i * C,
            enc_Wg + (size_t)i * C * C * 2, enc_bg + i * C,
            enc_Wr + (size_t)i * C * C,     enc_br + i * C,
            enc_Ws + (size_t)i * C * C,     enc_bs + i * C,
            dil);
        src ^= 1;
    }

    pool_kernel<<<Bc * C, 256>>>();
    fc_kernel<<<Bc, LATENT>>>(fc_mu_W, fc_mu_b, fc_lv_W, fc_lv_b, eps, out);
    dec_kernel<<<Bc, C>>>(dec_in_W, dec_in_b, dec_Wf, dec_bf, dec_Wg, dec_bg,
                          dec_Wr, dec_br, out_W, out_b, out);
}

// round 6
// speedup vs baseline: 3.1158x; 3.1148x over previous
#include <cuda_runtime.h>
#include <cuda_bf16.h>
#include <math.h>
#include <stdint.h>

#define Bc 4
#define C 256
#define Tn 4096
#define LATENT 128
#define NENC 40
#define NDEC 10
#define NT 128

#define STAGE_BYTES 65536
#define SMEM_TOTAL  131072
#define EXST 68            // exchange row stride in floats (64 + 4 pad)

// ---------------- device scratch ----------------
__device__ __align__(16) unsigned char g_wp1[(size_t)NENC * 2 * 8 * 4 * 16384]; // 40MB
__device__ __align__(16) unsigned char g_wp2[(size_t)NENC * 2 * 4 * 4 * 16384]; // 20MB
__device__ __align__(16) float         g_hf  [(size_t)Bc * Tn * C];
__device__ __align__(16) __nv_bfloat16 g_hhi [(size_t)Bc * Tn * C];
__device__ __align__(16) __nv_bfloat16 g_hlo [(size_t)Bc * Tn * C];
__device__ __align__(16) __nv_bfloat16 g_ghi [(size_t)Bc * Tn * C];
__device__ __align__(16) __nv_bfloat16 g_glo [(size_t)Bc * Tn * C];
__device__ __align__(16) float         g_skip[(size_t)Bc * Tn * C];
__device__ float g_poolp[Bc * 32 * C];
__device__ float g_pooled[Bc * C];
__device__ float g_z[Bc * LATENT];

// ---------------- helpers ----------------
__device__ __forceinline__ uint32_t smem_u32(const void* p) {
    uint32_t a;
    asm("{ .reg .u64 t; cvta.to.shared.u64 t, %1; cvt.u32.u64 %0, t; }" : "=r"(a) : "l"(p));
    return a;
}
__device__ __forceinline__ uint32_t swz(uint32_t off) { return off ^ ((off >> 3) & 0x70); }
__device__ __forceinline__ void cp16(uint32_t dst, const void* src, int sz) {
    asm volatile("cp.async.cg.shared.global [%0], [%1], 16, %2;"
                 :: "r"(dst), "l"(src), "r"(sz) : "memory");
}
#define LDSM4(r, addr) \
    asm volatile("ldmatrix.sync.aligned.m8n8.x4.shared.b16 {%0,%1,%2,%3}, [%4];" \
                 : "=r"((r)[0]), "=r"((r)[1]), "=r"((r)[2]), "=r"((r)[3]) : "r"(addr))
#define MMA(c, a, b0r, b1r) \
    asm volatile("mma.sync.aligned.m16n8k16.row.col.f32.bf16.bf16.f32 " \
                 "{%0,%1,%2,%3}, {%4,%5,%6,%7}, {%8,%9}, {%0,%1,%2,%3};" \
                 : "+f"((c)[0]), "+f"((c)[1]), "+f"((c)[2]), "+f"((c)[3]) \
                 : "r"((a)[0]), "r"((a)[1]), "r"((a)[2]), "r"((a)[3]), "r"(b0r), "r"(b1r))

__device__ __forceinline__ void split2(float v, __nv_bfloat16& h, __nv_bfloat16& l) {
    h = __float2bfloat16(v);
    l = __float2bfloat16(v - __bfloat162float(h));
}
__device__ __forceinline__ uint32_t pack2(__nv_bfloat16 a, __nv_bfloat16 b) {
    return (uint32_t)__bfloat16_as_ushort(a) | ((uint32_t)__bfloat16_as_ushort(b) << 16);
}

// ---------------- weight pre-pack ----------------
// wp1: [layer][oh][chunk 8][ms 4: f_hi,f_lo,g_hi,g_lo][16384B]; chunk: tap=kc>>2, c0=(kc&3)*64
__global__ void prep1_kernel(const float* __restrict__ Wf, const float* __restrict__ Wg) {
    size_t idx = (size_t)blockIdx.x * 256 + threadIdx.x;   // 2,621,440
    int j2 = idx & 31;
    int r  = (idx >> 5) & 127;
    int kc = (idx >> 12) & 7;
    int oh = (idx >> 15) & 1;
    int l  = (int)(idx >> 16);
    int o = oh * 128 + r;
    int tap = kc >> 2;
    int c = (kc & 3) * 64 + j2 * 2;
    uint32_t boff = swz((uint32_t)(r * 128 + j2 * 4));
    unsigned char* base = g_wp1 + ((((size_t)(l * 2 + oh) * 8 + kc) * 4) << 14) + boff;
    const float* pf = Wf + (((size_t)l * C + o) * C + c) * 2 + tap;
    const float* pg = Wg + (((size_t)l * C + o) * C + c) * 2 + tap;
    __nv_bfloat16 h0, l0, h1, l1;
    split2(pf[0], h0, l0); split2(pf[2], h1, l1);
    *(uint32_t*)(base)             = pack2(h0, h1);
    *(uint32_t*)(base + 16384)     = pack2(l0, l1);
    split2(pg[0], h0, l0); split2(pg[2], h1, l1);
    *(uint32_t*)(base + 2 * 16384) = pack2(h0, h1);
    *(uint32_t*)(base + 3 * 16384) = pack2(l0, l1);
}
// wp2: [layer][oh][chunk 4][ms 4: r_hi,r_lo,s_hi,s_lo][16384B]
__global__ void prep2_kernel(const float* __restrict__ Wr, const float* __restrict__ Ws) {
    size_t idx = (size_t)blockIdx.x * 256 + threadIdx.x;   // 1,310,720
    int j2 = idx & 31;
    int r  = (idx >> 5) & 127;
    int kc = (idx >> 12) & 3;
    int oh = (idx >> 14) & 1;
    int l  = (int)(idx >> 15);
    int o = oh * 128 + r;
    int c = kc * 64 + j2 * 2;
    uint32_t boff = swz((uint32_t)(r * 128 + j2 * 4));
    unsigned char* base = g_wp2 + ((((size_t)(l * 2 + oh) * 4 + kc) * 4) << 14) + boff;
    const float* pr = Wr + ((size_t)l * C + o) * C + c;
    const float* ps = Ws + ((size_t)l * C + o) * C + c;
    __nv_bfloat16 h0, l0, h1, l1;
    split2(pr[0], h0, l0); split2(pr[1], h1, l1);
    *(uint32_t*)(base)             = pack2(h0, h1);
    *(uint32_t*)(base + 16384)     = pack2(l0, l1);
    split2(ps[0], h0, l0); split2(ps[1], h1, l1);
    *(uint32_t*)(base + 2 * 16384) = pack2(h0, h1);
    *(uint32_t*)(base + 3 * 16384) = pack2(l0, l1);
}

// ---------------- encoder input conv ----------------
__global__ void enc_in_kernel(const float* __restrict__ x,
                              const float* __restrict__ W,
                              const float* __restrict__ bias) {
    size_t idx = (size_t)blockIdx.x * 256 + threadIdx.x;   // ((b*Tn+t)*C + c)
    int c = idx & 255;
    int t = (int)((idx >> 8) & 4095);
    int b = (int)(idx >> 20);
    float xc = x[b * Tn + t];
    float xp = (t > 0) ? x[b * Tn + t - 1] : 0.f;
    float h = W[c * 2] * xp + W[c * 2 + 1] * xc + bias[c];
    g_hf[idx] = h;
    __nv_bfloat16 hh, hl;
    split2(h, hh, hl);
    g_hhi[idx] = hh;
    g_hlo[idx] = hl;
    g_skip[idx] = 0.f;
}

// ---------------- unified bf16x3 mma.sync GEMM kernel ----------------
// mode 0: conv f/g (8 K-chunks, dilation). mode 1: res/skip 1x1 (4 K-chunks).
// grid (Bc*32, 4), 256 threads. Each CTA: 128 timesteps x 64 out-channels, 2 matrices.
__global__ void __launch_bounds__(256, 1)
gemm_kernel(int layer, int dil, int mode,
            const float* __restrict__ b0_, const float* __restrict__ b1_) {
    extern __shared__ unsigned char sm[];
    uint32_t smb = smem_u32(sm);
    const int tid = threadIdx.x, wid = tid >> 5, lane = tid & 31;
    const int b = blockIdx.x >> 5, tile = blockIdx.x & 31;
    const int oh2 = blockIdx.y;
    const int t0 = tile * NT;
    const int cg0 = oh2 * 64, oh = oh2 >> 1, slice = oh2 & 1;
    const int nch = mode ? 4 : 8;
    const int wm = wid & 3, sel = wid >> 2;

    const unsigned char* wbase = mode
        ? g_wp2 + ((size_t)(layer * 2 + oh) << 18)
        : g_wp1 + ((size_t)(layer * 2 + oh) << 19);
    const __nv_bfloat16* ahi = mode ? g_ghi : g_hhi;
    const __nv_bfloat16* alo = mode ? g_glo : g_hlo;

    auto load_chunk = [&](int kc, int s) {
        uint32_t stb = smb + (uint32_t)s * STAGE_BYTES;
        int toff = (!mode && (kc >> 2) == 0) ? dil : 0;
        int c0 = mode ? kc * 64 : (kc & 3) * 64;
        #pragma unroll
        for (int it = 0; it < 16; ++it) {
            int idx = it * 256 + tid;
            if (idx < 2048) {                        // A tiles hi/lo: 128 rows x 128B
                int sp = idx >> 10, seg = idx & 1023;
                int r = seg >> 3, j = seg & 7;
                int t = t0 + r - toff;
                int tc = t < 0 ? 0 : t;
                const __nv_bfloat16* s0 = sp ? alo : ahi;
                const char* src = (const char*)(s0 + ((size_t)b * Tn + tc) * C + c0) + j * 16;
                cp16(stb + sp * 16384 + swz((uint32_t)(r * 128 + j * 16)), src, t >= 0 ? 16 : 0);
            } else {                                 // B: 4 matrices, 64-row slice, pre-swizzled
                int bi = idx - 2048;                 // 0..2047
                int ms = bi >> 9, seg = bi & 511;
                const unsigned char* src = wbase + ((size_t)kc << 16) + (size_t)ms * 16384
                                         + (size_t)slice * 8192 + (size_t)seg * 16;
                cp16(stb + 32768 + (uint32_t)(ms * 8192 + seg * 16), src, 16);
            }
        }
        asm volatile("cp.async.commit_group;" ::: "memory");
    };

    load_chunk(0, 0);
    if (nch > 1) load_chunk(1, 1);

    float acc[2][8][4];
    #pragma unroll
    for (int mt = 0; mt < 2; ++mt)
        #pragma unroll
        for (int nt = 0; nt < 8; ++nt)
            #pragma unroll
            for (int q = 0; q < 4; ++q) acc[mt][nt][q] = 0.f;

    const int laneA_r = lane & 15, laneA_j = lane >> 4;
    const int laneB_r = ((lane >> 4) << 3) + (lane & 7), laneB_j = (lane >> 3) & 1;

    for (int i = 0; i < nch; ++i) {
        int s = i & 1;
        if (i + 1 < nch) asm volatile("cp.async.wait_group 1;" ::: "memory");
        else             asm volatile("cp.async.wait_group 0;" ::: "memory");
        __syncthreads();
        uint32_t stb = smb + (uint32_t)s * STAGE_BYTES;
        uint32_t aH = stb, aL = stb + 16384;
        uint32_t bH = stb + 32768 + (uint32_t)sel * 16384, bL = bH + 8192;
        #pragma unroll
        for (int ks = 0; ks < 4; ++ks) {
            uint32_t ah[2][4], al[2][4];
            #pragma unroll
            for (int mt = 0; mt < 2; ++mt) {
                uint32_t off = swz((uint32_t)((wm * 32 + mt * 16 + laneA_r) * 128
                                              + (ks * 2 + laneA_j) * 16));
                LDSM4(ah[mt], aH + off);
                LDSM4(al[mt], aL + off);
            }
            #pragma unroll
            for (int np = 0; np < 4; ++np) {
                uint32_t offB = swz((uint32_t)((np * 16 + laneB_r) * 128
                                               + (ks * 2 + laneB_j) * 16));
                uint32_t bh[4], bl[4];
                LDSM4(bh, bH + offB);
                LDSM4(bl, bL + offB);
                int n0 = 2 * np, n1 = 2 * np + 1;
                MMA(acc[0][n0], ah[0], bh[0], bh[1]);
                MMA(acc[1][n0], ah[1], bh[0], bh[1]);
                MMA(acc[0][n1], ah[0], bh[2], bh[3]);
                MMA(acc[1][n1], ah[1], bh[2], bh[3]);
                MMA(acc[0][n0], al[0], bh[0], bh[1]);
                MMA(acc[1][n0], al[1], bh[0], bh[1]);
                MMA(acc[0][n1], al[0], bh[2], bh[3]);
                MMA(acc[1][n1], al[1], bh[2], bh[3]);
                MMA(acc[0][n0], ah[0], bl[0], bl[1]);
                MMA(acc[1][n0], ah[1], bl[0], bl[1]);
                MMA(acc[0][n1], ah[0], bl[2], bl[3]);
                MMA(acc[1][n1], ah[1], bl[2], bl[3]);
            }
        }
        __syncthreads();
        if (i + 2 < nch) load_chunk(i + 2, s);
    }

    // ---- exchange through smem: matrix0 (f / res) and matrix1 (g / skip) ----
    float* exf = (float*)sm;                       // [128][EXST]
    float* exg = (float*)(sm + 128 * EXST * 4);
    float* exw = sel ? exg : exf;
    #pragma unroll
    for (int mt = 0; mt < 2; ++mt)
        #pragma unroll
        for (int nt = 0; nt < 8; ++nt) {
            int row = wm * 32 + mt * 16 + (lane >> 2);
            int col = nt * 8 + 2 * (lane & 3);
            exw[row * EXST + col]           = acc[mt][nt][0];
            exw[row * EXST + col + 1]       = acc[mt][nt][1];
            exw[(row + 8) * EXST + col]     = acc[mt][nt][2];
            exw[(row + 8) * EXST + col + 1] = acc[mt][nt][3];
        }
    __syncthreads();

    // ---- fused epilogue ----
    if (mode == 0) {
        #pragma unroll
        for (int e = 0; e < 16; ++e) {
            int idx2 = e * 256 + tid;          // 4096 channel-pairs
            int row = idx2 >> 5, cp = (idx2 & 31) * 2;
            int c = cg0 + cp;
            float f0 = exf[row * EXST + cp]     + b0_[c];
            float f1 = exf[row * EXST + cp + 1] + b0_[c + 1];
            float g0 = exg[row * EXST + cp]     + b1_[c];
            float g1 = exg[row * EXST + cp + 1] + b1_[c + 1];
            float v0 = tanhf(f0) / (1.f + expf(-g0));
            float v1 = tanhf(f1) / (1.f + expf(-g1));
            __nv_bfloat16 h0, l0, h1, l1;
            split2(v0, h0, l0); split2(v1, h1, l1);
            size_t base = ((size_t)b * Tn + t0 + row) * C + c;
            *(uint32_t*)(g_ghi + base) = pack2(h0, h1);
            *(uint32_t*)(g_glo + base) = pack2(l0, l1);
        }
    } else {
        #pragma unroll
        for (int e = 0; e < 16; ++e) {
            int idx2 = e * 256 + tid;
            int row = idx2 >> 5, cp = (idx2 & 31) * 2;
            int c = cg0 + cp;
            size_t base = ((size_t)b * Tn + t0 + row) * C + c;
            float2 hv = *(float2*)(g_hf + base);
            float n0 = exf[row * EXST + cp]     + b0_[c]     + hv.x;
            float n1 = exf[row * EXST + cp + 1] + b0_[c + 1] + hv.y;
            *(float2*)(g_hf + base) = make_float2(n0, n1);
            float2 sv = *(float2*)(g_skip + base);
            sv.x += exg[row * EXST + cp]     + b1_[c];
            sv.y += exg[row * EXST + cp + 1] + b1_[c + 1];
            *(float2*)(g_skip + base) = sv;
            __nv_bfloat16 h0, l0, h1, l1;
            split2(n0, h0, l0); split2(n1, h1, l1);
            *(uint32_t*)(g_hhi + base) = pack2(h0, h1);
            *(uint32_t*)(g_hlo + base) = pack2(l0, l1);
        }
    }
}

// ---------------- pooling ----------------
__global__ void pool1_kernel() {           // grid Bc*32, 256 thr
    int b = blockIdx.x >> 5, tc = blockIdx.x & 31;
    int c = threadIdx.x;
    float s = 0.f;
    size_t base = ((size_t)b * Tn + tc * 128) * C + c;
    for (int t = 0; t < 128; ++t) s += g_skip[base + (size_t)t * C];
    g_poolp[blockIdx.x * C + c] = s;
}
__global__ void pool2_kernel() {           // grid Bc, 256 thr
    int b = blockIdx.x, c = threadIdx.x;
    float s = 0.f;
    for (int i = 0; i < 32; ++i) s += g_poolp[(b * 32 + i) * C + c];
    g_pooled[b * C + c] = s * (1.f / Tn);
}

// ---------------- mu / logvar / reparameterize ----------------
__global__ void fc_kernel(const float* __restrict__ muW, const float* __restrict__ mub,
                          const float* __restrict__ lvW, const float* __restrict__ lvb,
                          const float* __restrict__ eps, float* __restrict__ out) {
    int b = blockIdx.x, l = threadIdx.x;
    const float* p = g_pooled + b * C;
    float m0 = mub[l], m1 = 0.f, v0 = lvb[l], v1 = 0.f;
    const float* wm = muW + l * C;
    const float* wv = lvW + l * C;
    for (int c = 0; c < C; c += 2) {
        m0 += wm[c] * p[c];     m1 += wm[c + 1] * p[c + 1];
        v0 += wv[c] * p[c];     v1 += wv[c + 1] * p[c + 1];
    }
    float mu = m0 + m1, lv = v0 + v1;
    out[4 + b * LATENT + l] = mu;
    out[4 + Bc * LATENT + b * LATENT + l] = lv;
    g_z[b * LATENT + l] = mu + eps[b * LATENT + l] * expf(0.5f * lv);
}

// ---------------- decoder (T=1: only tap 1 of each k=2 conv contributes) ----------------
__global__ void dec_kernel(const float* __restrict__ inW, const float* __restrict__ inb,
                           const float* __restrict__ Wf, const float* __restrict__ bf,
                           const float* __restrict__ Wg, const float* __restrict__ bg,
                           const float* __restrict__ Wr, const float* __restrict__ br,
                           const float* __restrict__ outW, const float* __restrict__ outb,
                           float* __restrict__ out) {
    __shared__ float h2[C], fg[C], red[C];
    int b = blockIdx.x, c = threadIdx.x;
    {
        float s = inb[c];
        const float* w = inW + c * LATENT;
        const float* zz = g_z + b * LATENT;
        for (int l = 0; l < LATENT; ++l) s += w[l] * zz[l];
        h2[c] = s;
    }
    __syncthreads();
    for (int i = 0; i < NDEC; ++i) {
        const float* wf = Wf + (size_t)(i * C + c) * C * 2;
        const float* wg = Wg + (size_t)(i * C + c) * C * 2;
        float f0 = bf[i * C + c], f1 = 0.f, g0 = bg[i * C + c], g1 = 0.f;
        for (int cc = 0; cc < C; cc += 2) {
            float h0 = h2[cc], h1 = h2[cc + 1];
            f0 += wf[cc * 2 + 1] * h0;  f1 += wf[cc * 2 + 3] * h1;
            g0 += wg[cc * 2 + 1] * h0;  g1 += wg[cc * 2 + 3] * h1;
        }
        float fv = f0 + f1, gv = g0 + g1;
        fg[c] = tanhf(fv) / (1.f + expf(-gv));
        __syncthreads();
        const float* wr = Wr + (size_t)(i * C + c) * C;
        float r0 = br[i * C + c], r1 = 0.f;
        for (int cc = 0; cc < C; cc += 2) {
            r0 += wr[cc] * fg[cc];
            r1 += wr[cc + 1] * fg[cc + 1];
        }
        h2[c] += r0 + r1;
        __syncthreads();
    }
    red[c] = outW[c] * h2[c];
    __syncthreads();
    for (int off = 128; off; off >>= 1) {
        if (c < off) red[c] += red[c + off];
        __syncthreads();
    }
    if (c == 0) out[b] = red[0] + outb[0];
}

// ---------------- host ----------------
extern "C" void kernel_launch(void* const* d_in, const int* in_sizes, int n_in,
                              void* d_out, int out_size) {
    const float* x        = (const float*)d_in[0];
    const float* eps      = (const float*)d_in[1];
    const float* enc_in_W = (const float*)d_in[2];
    const float* enc_in_b = (const float*)d_in[3];
    const float* enc_Wf   = (const float*)d_in[4];
    const float* enc_bf   = (const float*)d_in[5];
    const float* enc_Wg   = (const float*)d_in[6];
    const float* enc_bg   = (const float*)d_in[7];
    const float* enc_Wr   = (const float*)d_in[8];
    const float* enc_br   = (const float*)d_in[9];
    const float* enc_Ws   = (const float*)d_in[10];
    const float* enc_bs   = (const float*)d_in[11];
    const float* fc_mu_W  = (const float*)d_in[12];
    const float* fc_mu_b  = (const float*)d_in[13];
    const float* fc_lv_W  = (const float*)d_in[14];
    const float* fc_lv_b  = (const float*)d_in[15];
    const float* dec_in_W = (const float*)d_in[16];
    const float* dec_in_b = (const float*)d_in[17];
    const float* dec_Wf   = (const float*)d_in[18];
    const float* dec_bf   = (const float*)d_in[19];
    const float* dec_Wg   = (const float*)d_in[20];
    const float* dec_bg   = (const float*)d_in[21];
    const float* dec_Wr   = (const float*)d_in[22];
    const float* dec_br   = (const float*)d_in[23];
    const float* out_W    = (const float*)d_in[24];
    const float* out_b    = (const float*)d_in[25];
    float* out = (float*)d_out;

    cudaFuncSetAttribute(gemm_kernel, cudaFuncAttributeMaxDynamicSharedMemorySize, SMEM_TOTAL);

    prep1_kernel<<<10240, 256>>>(enc_Wf, enc_Wg);
    prep2_kernel<<<5120, 256>>>(enc_Wr, enc_Ws);
    enc_in_kernel<<<(Bc * Tn * C) / 256, 256>>>(x, enc_in_W, enc_in_b);

    for (int i = 0; i < NENC; ++i) {
        int dil = 1 << (i % 10);
        gemm_kernel<<<dim3(Bc * 32, 4), 256, SMEM_TOTAL>>>(i, dil, 0,
                                                           enc_bf + i * C, enc_bg + i * C);
        gemm_kernel<<<dim3(Bc * 32, 4), 256, SMEM_TOTAL>>>(i, 0, 1,
                                                           enc_br + i * C, enc_bs + i * C);
    }

    pool1_kernel<<<Bc * 32, 256>>>();
    pool2_kernel<<<Bc, 256>>>();
    fc_kernel<<<Bc, LATENT>>>(fc_mu_W, fc_mu_b, fc_lv_W, fc_lv_b, eps, out);
    dec_kernel<<<Bc, C>>>(dec_in_W, dec_in_b, dec_Wf, dec_bf, dec_Wg, dec_bg,
                          dec_Wr, dec_br, out_W, out_b, out);
}

// round 7
// speedup vs baseline: 3.4361x; 1.1028x over previous
#include <cuda_runtime.h>
#include <cuda_bf16.h>
#include <math.h>
#include <stdint.h>

#define Bc 4
#define C 256
#define Tn 4096
#define LATENT 128
#define NENC 40
#define NDEC 10
#define NT 128

#define STAGE_BYTES 65536
#define SMEM_TOTAL (3 * STAGE_BYTES)
#define EXST 68            // exchange row stride in floats (64 + 4 pad)

// ---------------- device scratch ----------------
__device__ __align__(16) unsigned char g_wp1[(size_t)NENC * 2 * 8 * 4 * 16384]; // 40MB
__device__ __align__(16) unsigned char g_wp2[(size_t)NENC * 2 * 4 * 4 * 16384]; // 20MB
__device__ __align__(16) float         g_hf  [(size_t)Bc * Tn * C];
__device__ __align__(16) __nv_bfloat16 g_hhi [(size_t)Bc * Tn * C];
__device__ __align__(16) __nv_bfloat16 g_hlo [(size_t)Bc * Tn * C];
__device__ __align__(16) __nv_bfloat16 g_ghi [(size_t)Bc * Tn * C];
__device__ __align__(16) __nv_bfloat16 g_glo [(size_t)Bc * Tn * C];
__device__ __align__(16) float         g_skip[(size_t)Bc * Tn * C];
__device__ float g_poolp[Bc * 32 * C];
__device__ float g_pooled[Bc * C];
__device__ float g_z[Bc * LATENT];

// ---------------- helpers ----------------
__device__ __forceinline__ uint32_t smem_u32(const void* p) {
    uint32_t a;
    asm("{ .reg .u64 t; cvta.to.shared.u64 t, %1; cvt.u32.u64 %0, t; }" : "=r"(a) : "l"(p));
    return a;
}
__device__ __forceinline__ uint32_t swz(uint32_t off) { return off ^ ((off >> 3) & 0x70); }
__device__ __forceinline__ void cp16(uint32_t dst, const void* src, int sz) {
    asm volatile("cp.async.cg.shared.global [%0], [%1], 16, %2;"
                 :: "r"(dst), "l"(src), "r"(sz) : "memory");
}
#define LDSM4(r, addr) \
    asm volatile("ldmatrix.sync.aligned.m8n8.x4.shared.b16 {%0,%1,%2,%3}, [%4];" \
                 : "=r"((r)[0]), "=r"((r)[1]), "=r"((r)[2]), "=r"((r)[3]) : "r"(addr))
#define MMA(c, a, b0r, b1r) \
    asm volatile("mma.sync.aligned.m16n8k16.row.col.f32.bf16.bf16.f32 " \
                 "{%0,%1,%2,%3}, {%4,%5,%6,%7}, {%8,%9}, {%0,%1,%2,%3};" \
                 : "+f"((c)[0]), "+f"((c)[1]), "+f"((c)[2]), "+f"((c)[3]) \
                 : "r"((a)[0]), "r"((a)[1]), "r"((a)[2]), "r"((a)[3]), "r"(b0r), "r"(b1r))

__device__ __forceinline__ void split2(float v, __nv_bfloat16& h, __nv_bfloat16& l) {
    h = __float2bfloat16(v);
    l = __float2bfloat16(v - __bfloat162float(h));
}
__device__ __forceinline__ uint32_t pack2(__nv_bfloat16 a, __nv_bfloat16 b) {
    return (uint32_t)__bfloat16_as_ushort(a) | ((uint32_t)__bfloat16_as_ushort(b) << 16);
}

// ---------------- weight pre-pack ----------------
// wp1: [layer][oh][chunk 8][ms 4: f_hi,f_lo,g_hi,g_lo][16384B]; chunk: tap=kc>>2, c0=(kc&3)*64
__global__ void prep1_kernel(const float* __restrict__ Wf, const float* __restrict__ Wg) {
    size_t idx = (size_t)blockIdx.x * 256 + threadIdx.x;   // 2,621,440
    int j2 = idx & 31;
    int r  = (idx >> 5) & 127;
    int kc = (idx >> 12) & 7;
    int oh = (idx >> 15) & 1;
    int l  = (int)(idx >> 16);
    int o = oh * 128 + r;
    int tap = kc >> 2;
    int c = (kc & 3) * 64 + j2 * 2;
    uint32_t boff = swz((uint32_t)(r * 128 + j2 * 4));
    unsigned char* base = g_wp1 + ((((size_t)(l * 2 + oh) * 8 + kc) * 4) << 14) + boff;
    const float* pf = Wf + (((size_t)l * C + o) * C + c) * 2 + tap;
    const float* pg = Wg + (((size_t)l * C + o) * C + c) * 2 + tap;
    __nv_bfloat16 h0, l0, h1, l1;
    split2(pf[0], h0, l0); split2(pf[2], h1, l1);
    *(uint32_t*)(base)             = pack2(h0, h1);
    *(uint32_t*)(base + 16384)     = pack2(l0, l1);
    split2(pg[0], h0, l0); split2(pg[2], h1, l1);
    *(uint32_t*)(base + 2 * 16384) = pack2(h0, h1);
    *(uint32_t*)(base + 3 * 16384) = pack2(l0, l1);
}
// wp2: [layer][oh][chunk 4][ms 4: r_hi,r_lo,s_hi,s_lo][16384B]
__global__ void prep2_kernel(const float* __restrict__ Wr, const float* __restrict__ Ws) {
    size_t idx = (size_t)blockIdx.x * 256 + threadIdx.x;   // 1,310,720
    int j2 = idx & 31;
    int r  = (idx >> 5) & 127;
    int kc = (idx >> 12) & 3;
    int oh = (idx >> 14) & 1;
    int l  = (int)(idx >> 15);
    int o = oh * 128 + r;
    int c = kc * 64 + j2 * 2;
    uint32_t boff = swz((uint32_t)(r * 128 + j2 * 4));
    unsigned char* base = g_wp2 + ((((size_t)(l * 2 + oh) * 4 + kc) * 4) << 14) + boff;
    const float* pr = Wr + ((size_t)l * C + o) * C + c;
    const float* ps = Ws + ((size_t)l * C + o) * C + c;
    __nv_bfloat16 h0, l0, h1, l1;
    split2(pr[0], h0, l0); split2(pr[1], h1, l1);
    *(uint32_t*)(base)             = pack2(h0, h1);
    *(uint32_t*)(base + 16384)     = pack2(l0, l1);
    split2(ps[0], h0, l0); split2(ps[1], h1, l1);
    *(uint32_t*)(base + 2 * 16384) = pack2(h0, h1);
    *(uint32_t*)(base + 3 * 16384) = pack2(l0, l1);
}

// ---------------- encoder input conv ----------------
__global__ void enc_in_kernel(const float* __restrict__ x,
                              const float* __restrict__ W,
                              const float* __restrict__ bias) {
    size_t idx = (size_t)blockIdx.x * 256 + threadIdx.x;   // ((b*Tn+t)*C + c)
    int c = idx & 255;
    int t = (int)((idx >> 8) & 4095);
    int b = (int)(idx >> 20);
    float xc = x[b * Tn + t];
    float xp = (t > 0) ? x[b * Tn + t - 1] : 0.f;
    float h = W[c * 2] * xp + W[c * 2 + 1] * xc + bias[c];
    g_hf[idx] = h;
    __nv_bfloat16 hh, hl;
    split2(h, hh, hl);
    g_hhi[idx] = hh;
    g_hlo[idx] = hl;
    g_skip[idx] = 0.f;
}

// ---------------- unified bf16x3 mma.sync GEMM kernel ----------------
// mode 0: conv f/g (8 K-chunks, dilation). mode 1: res/skip 1x1 (4 K-chunks).
// grid (Bc*32, 4), 512 threads. CTA: 128 timesteps x 64 out-channels, 2 matrices.
// 16 warps = 4(M) x 2(N-half) x 2(matrix-select); per-warp tile 32x32.
__global__ void __launch_bounds__(512, 1)
gemm_kernel(int layer, int dil, int mode,
            const float* __restrict__ b0_, const float* __restrict__ b1_) {
    extern __shared__ unsigned char sm[];
    uint32_t smb = smem_u32(sm);
    const int tid = threadIdx.x, wid = tid >> 5, lane = tid & 31;
    const int b = blockIdx.x >> 5, tile = blockIdx.x & 31;
    const int oh2 = blockIdx.y;
    const int t0 = tile * NT;
    const int cg0 = oh2 * 64, oh = oh2 >> 1, slice = oh2 & 1;
    const int nch = mode ? 4 : 8;
    const int wm = wid & 3, ns = (wid >> 2) & 1, sel = wid >> 3;

    const unsigned char* wbase = mode
        ? g_wp2 + ((size_t)(layer * 2 + oh) << 18)
        : g_wp1 + ((size_t)(layer * 2 + oh) << 19);
    const __nv_bfloat16* ahi = mode ? g_ghi : g_hhi;
    const __nv_bfloat16* alo = mode ? g_glo : g_hlo;

    auto load_chunk = [&](int kc, int s) {
        uint32_t stb = smb + (uint32_t)s * STAGE_BYTES;
        int toff = (!mode && (kc >> 2) == 0) ? dil : 0;
        int c0 = mode ? kc * 64 : (kc & 3) * 64;
        #pragma unroll
        for (int it = 0; it < 8; ++it) {
            int idx = it * 512 + tid;
            if (idx < 2048) {                        // A tiles hi/lo: 128 rows x 128B
                int sp = idx >> 10, seg = idx & 1023;
                int r = seg >> 3, j = seg & 7;
                int t = t0 + r - toff;
                int tc = t < 0 ? 0 : t;
                const __nv_bfloat16* s0 = sp ? alo : ahi;
                const char* src = (const char*)(s0 + ((size_t)b * Tn + tc) * C + c0) + j * 16;
                cp16(stb + sp * 16384 + swz((uint32_t)(r * 128 + j * 16)), src, t >= 0 ? 16 : 0);
            } else {                                 // B: 4 matrices, 64-row slice, pre-swizzled
                int bi = idx - 2048;                 // 0..2047
                int ms = bi >> 9, seg = bi & 511;
                const unsigned char* src = wbase + ((size_t)kc << 16) + (size_t)ms * 16384
                                         + (size_t)slice * 8192 + (size_t)seg * 16;
                cp16(stb + 32768 + (uint32_t)(ms * 8192 + seg * 16), src, 16);
            }
        }
        asm volatile("cp.async.commit_group;" ::: "memory");
    };

    load_chunk(0, 0);
    if (nch > 1) load_chunk(1, 1);

    float acc[2][4][4];
    #pragma unroll
    for (int mt = 0; mt < 2; ++mt)
        #pragma unroll
        for (int nt = 0; nt < 4; ++nt)
            #pragma unroll
            for (int q = 0; q < 4; ++q) acc[mt][nt][q] = 0.f;

    const int laneA_r = lane & 15, laneA_j = lane >> 4;
    const int laneB_r = ((lane >> 4) << 3) + (lane & 7), laneB_j = (lane >> 3) & 1;

    for (int i = 0; i < nch; ++i) {
        int s = i % 3;
        if (i + 1 < nch) asm volatile("cp.async.wait_group 1;" ::: "memory");
        else             asm volatile("cp.async.wait_group 0;" ::: "memory");
        __syncthreads();
        if (i + 2 < nch) load_chunk(i + 2, (i + 2) % 3);   // stage freed at iter i-1

        uint32_t stb = smb + (uint32_t)s * STAGE_BYTES;
        uint32_t aH = stb, aL = stb + 16384;
        uint32_t bH = stb + 32768 + (uint32_t)sel * 16384, bL = bH + 8192;
        #pragma unroll
        for (int ks = 0; ks < 4; ++ks) {
            uint32_t ah[2][4], al[2][4];
            #pragma unroll
            for (int mt = 0; mt < 2; ++mt) {
                uint32_t off = swz((uint32_t)((wm * 32 + mt * 16 + laneA_r) * 128
                                              + (ks * 2 + laneA_j) * 16));
                LDSM4(ah[mt], aH + off);
                LDSM4(al[mt], aL + off);
            }
            #pragma unroll
            for (int np = 0; np < 2; ++np) {
                uint32_t offB = swz((uint32_t)((ns * 32 + np * 16 + laneB_r) * 128
                                               + (ks * 2 + laneB_j) * 16));
                uint32_t bh[4], bl[4];
                LDSM4(bh, bH + offB);
                LDSM4(bl, bL + offB);
                int n0 = np * 2, n1 = np * 2 + 1;
                MMA(acc[0][n0], ah[0], bh[0], bh[1]);
                MMA(acc[1][n0], ah[1], bh[0], bh[1]);
                MMA(acc[0][n1], ah[0], bh[2], bh[3]);
                MMA(acc[1][n1], ah[1], bh[2], bh[3]);
                MMA(acc[0][n0], al[0], bh[0], bh[1]);
                MMA(acc[1][n0], al[1], bh[0], bh[1]);
                MMA(acc[0][n1], al[0], bh[2], bh[3]);
                MMA(acc[1][n1], al[1], bh[2], bh[3]);
                MMA(acc[0][n0], ah[0], bl[0], bl[1]);
                MMA(acc[1][n0], ah[1], bl[0], bl[1]);
                MMA(acc[0][n1], ah[0], bl[2], bl[3]);
                MMA(acc[1][n1], ah[1], bl[2], bl[3]);
            }
        }
    }
    __syncthreads();   // all MMA reads of smem done before exchange overwrite

    // ---- exchange through smem: matrix0 (f / res) and matrix1 (g / skip) ----
    float* exf = (float*)sm;                       // [128][EXST]
    float* exg = (float*)(sm + 128 * EXST * 4);
    float* exw = sel ? exg : exf;
    #pragma unroll
    for (int mt = 0; mt < 2; ++mt)
        #pragma unroll
        for (int nt = 0; nt < 4; ++nt) {
            int row = wm * 32 + mt * 16 + (lane >> 2);
            int col = ns * 32 + (nt >> 1) * 16 + (nt & 1) * 8 + 2 * (lane & 3);
            exw[row * EXST + col]           = acc[mt][nt][0];
            exw[row * EXST + col + 1]       = acc[mt][nt][1];
            exw[(row + 8) * EXST + col]     = acc[mt][nt][2];
            exw[(row + 8) * EXST + col + 1] = acc[mt][nt][3];
        }
    __syncthreads();

    // ---- fused epilogue ----
    if (mode == 0) {
        #pragma unroll
        for (int e = 0; e < 8; ++e) {
            int idx2 = e * 512 + tid;          // 4096 channel-pairs
            int row = idx2 >> 5, cp = (idx2 & 31) * 2;
            int c = cg0 + cp;
            float f0 = exf[row * EXST + cp]     + b0_[c];
            float f1 = exf[row * EXST + cp + 1] + b0_[c + 1];
            float g0 = exg[row * EXST + cp]     + b1_[c];
            float g1 = exg[row * EXST + cp + 1] + b1_[c + 1];
            float v0 = tanhf(f0) / (1.f + expf(-g0));
            float v1 = tanhf(f1) / (1.f + expf(-g1));
            __nv_bfloat16 h0, l0, h1, l1;
            split2(v0, h0, l0); split2(v1, h1, l1);
            size_t base = ((size_t)b * Tn + t0 + row) * C + c;
            *(uint32_t*)(g_ghi + base) = pack2(h0, h1);
            *(uint32_t*)(g_glo + base) = pack2(l0, l1);
        }
    } else {
        #pragma unroll
        for (int e = 0; e < 8; ++e) {
            int idx2 = e * 512 + tid;
            int row = idx2 >> 5, cp = (idx2 & 31) * 2;
            int c = cg0 + cp;
            size_t base = ((size_t)b * Tn + t0 + row) * C + c;
            float2 hv = *(float2*)(g_hf + base);
            float n0 = exf[row * EXST + cp]     + b0_[c]     + hv.x;
            float n1 = exf[row * EXST + cp + 1] + b0_[c + 1] + hv.y;
            *(float2*)(g_hf + base) = make_float2(n0, n1);
            float2 sv = *(float2*)(g_skip + base);
            sv.x += exg[row * EXST + cp]     + b1_[c];
            sv.y += exg[row * EXST + cp + 1] + b1_[c + 1];
            *(float2*)(g_skip + base) = sv;
            __nv_bfloat16 h0, l0, h1, l1;
            split2(n0, h0, l0); split2(n1, h1, l1);
            *(uint32_t*)(g_hhi + base) = pack2(h0, h1);
            *(uint32_t*)(g_hlo + base) = pack2(l0, l1);
        }
    }
}

// ---------------- pooling ----------------
__global__ void pool1_kernel() {           // grid Bc*32, 256 thr
    int b = blockIdx.x >> 5, tc = blockIdx.x & 31;
    int c = threadIdx.x;
    float s = 0.f;
    size_t base = ((size_t)b * Tn + tc * 128) * C + c;
    for (int t = 0; t < 128; ++t) s += g_skip[base + (size_t)t * C];
    g_poolp[blockIdx.x * C + c] = s;
}
__global__ void pool2_kernel() {           // grid Bc, 256 thr
    int b = blockIdx.x, c = threadIdx.x;
    float s = 0.f;
    for (int i = 0; i < 32; ++i) s += g_poolp[(b * 32 + i) * C + c];
    g_pooled[b * C + c] = s * (1.f / Tn);
}

// ---------------- mu / logvar / reparameterize ----------------
__global__ void fc_kernel(const float* __restrict__ muW, const float* __restrict__ mub,
                          const float* __restrict__ lvW, const float* __restrict__ lvb,
                          const float* __restrict__ eps, float* __restrict__ out) {
    int b = blockIdx.x, l = threadIdx.x;
    const float* p = g_pooled + b * C;
    float m0 = mub[l], m1 = 0.f, v0 = lvb[l], v1 = 0.f;
    const float* wm = muW + l * C;
    const float* wv = lvW + l * C;
    for (int c = 0; c < C; c += 2) {
        m0 += wm[c] * p[c];     m1 += wm[c + 1] * p[c + 1];
        v0 += wv[c] * p[c];     v1 += wv[c + 1] * p[c + 1];
    }
    float mu = m0 + m1, lv = v0 + v1;
    out[4 + b * LATENT + l] = mu;
    out[4 + Bc * LATENT + b * LATENT + l] = lv;
    g_z[b * LATENT + l] = mu + eps[b * LATENT + l] * expf(0.5f * lv);
}

// ---------------- decoder (T=1: only tap 1 of each k=2 conv contributes) ----------------
__global__ void dec_kernel(const float* __restrict__ inW, const float* __restrict__ inb,
                           const float* __restrict__ Wf, const float* __restrict__ bf,
                           const float* __restrict__ Wg, const float* __restrict__ bg,
                           const float* __restrict__ Wr, const float* __restrict__ br,
                           const float* __restrict__ outW, const float* __restrict__ outb,
                           float* __restrict__ out) {
    __shared__ float h2[C], fg[C], red[C];
    int b = blockIdx.x, c = threadIdx.x;
    {
        float s = inb[c];
        const float* w = inW + c * LATENT;
        const float* zz = g_z + b * LATENT;
        for (int l = 0; l < LATENT; ++l) s += w[l] * zz[l];
        h2[c] = s;
    }
    __syncthreads();
    for (int i = 0; i < NDEC; ++i) {
        const float* wf = Wf + (size_t)(i * C + c) * C * 2;
        const float* wg = Wg + (size_t)(i * C + c) * C * 2;
        float f0 = bf[i * C + c], f1 = 0.f, g0 = bg[i * C + c], g1 = 0.f;
        for (int cc = 0; cc < C; cc += 2) {
            float h0 = h2[cc], h1 = h2[cc + 1];
            f0 += wf[cc * 2 + 1] * h0;  f1 += wf[cc * 2 + 3] * h1;
            g0 += wg[cc * 2 + 1] * h0;  g1 += wg[cc * 2 + 3] * h1;
        }
        float fv = f0 + f1, gv = g0 + g1;
        fg[c] = tanhf(fv) / (1.f + expf(-gv));
        __syncthreads();
        const float* wr = Wr + (size_t)(i * C + c) * C;
        float r0 = br[i * C + c], r1 = 0.f;
        for (int cc = 0; cc < C; cc += 2) {
            r0 += wr[cc] * fg[cc];
            r1 += wr[cc + 1] * fg[cc + 1];
        }
        h2[c] += r0 + r1;
        __syncthreads();
    }
    red[c] = outW[c] * h2[c];
    __syncthreads();
    for (int off = 128; off; off >>= 1) {
        if (c < off) red[c] += red[c + off];
        __syncthreads();
    }
    if (c == 0) out[b] = red[0] + outb[0];
}

// ---------------- host ----------------
extern "C" void kernel_launch(void* const* d_in, const int* in_sizes, int n_in,
                              void* d_out, int out_size) {
    const float* x        = (const float*)d_in[0];
    const float* eps      = (const float*)d_in[1];
    const float* enc_in_W = (const float*)d_in[2];
    const float* enc_in_b = (const float*)d_in[3];
    const float* enc_Wf   = (const float*)d_in[4];
    const float* enc_bf   = (const float*)d_in[5];
    const float* enc_Wg   = (const float*)d_in[6];
    const float* enc_bg   = (const float*)d_in[7];
    const float* enc_Wr   = (const float*)d_in[8];
    const float* enc_br   = (const float*)d_in[9];
    const float* enc_Ws   = (const float*)d_in[10];
    const float* enc_bs   = (const float*)d_in[11];
    const float* fc_mu_W  = (const float*)d_in[12];
    const float* fc_mu_b  = (const float*)d_in[13];
    const float* fc_lv_W  = (const float*)d_in[14];
    const float* fc_lv_b  = (const float*)d_in[15];
    const float* dec_in_W = (const float*)d_in[16];
    const float* dec_in_b = (const float*)d_in[17];
    const float* dec_Wf   = (const float*)d_in[18];
    const float* dec_bf   = (const float*)d_in[19];
    const float* dec_Wg   = (const float*)d_in[20];
    const float* dec_bg   = (const float*)d_in[21];
    const float* dec_Wr   = (const float*)d_in[22];
    const float* dec_br   = (const float*)d_in[23];
    const float* out_W    = (const float*)d_in[24];
    const float* out_b    = (const float*)d_in[25];
    float* out = (float*)d_out;

    cudaFuncSetAttribute(gemm_kernel, cudaFuncAttributeMaxDynamicSharedMemorySize, SMEM_TOTAL);

    prep1_kernel<<<10240, 256>>>(enc_Wf, enc_Wg);
    prep2_kernel<<<5120, 256>>>(enc_Wr, enc_Ws);
    enc_in_kernel<<<(Bc * Tn * C) / 256, 256>>>(x, enc_in_W, enc_in_b);

    for (int i = 0; i < NENC; ++i) {
        int dil = 1 << (i % 10);
        gemm_kernel<<<dim3(Bc * 32, 4), 512, SMEM_TOTAL>>>(i, dil, 0,
                                                           enc_bf + i * C, enc_bg + i * C);
        gemm_kernel<<<dim3(Bc * 32, 4), 512, SMEM_TOTAL>>>(i, 0, 1,
                                                           enc_br + i * C, enc_bs + i * C);
    }

    pool1_kernel<<<Bc * 32, 256>>>();
    pool2_kernel<<<Bc, 256>>>();
    fc_kernel<<<Bc, LATENT>>>(fc_mu_W, fc_mu_b, fc_lv_W, fc_lv_b, eps, out);
    dec_kernel<<<Bc, C>>>(dec_in_W, dec_in_b, dec_Wf, dec_bf, dec_Wg, dec_bg,
                          dec_Wr, dec_br, out_W, out_b, out);
}

// round 9
// speedup vs baseline: 3.5849x; 1.0433x over previous
#include <cuda_runtime.h>
#include <cuda_bf16.h>
#include <math.h>
#include <stdint.h>

#define Bc 4
#define C 256
#define Tn 4096
#define LATENT 128
#define NENC 40
#define NDEC 10
#define NT 128

#define STAGE_BYTES 65536
#define NSTAGE 3
#define SMEM_TOTAL (NSTAGE * STAGE_BYTES)

// ---------------- device scratch ----------------
__device__ __align__(16) unsigned char g_wp1[(size_t)NENC * 2 * 8 * 4 * 16384]; // 40MB
__device__ __align__(16) unsigned char g_wp2[(size_t)NENC * 2 * 4 * 2 * 16384]; // 10MB
__device__ __align__(16) float         g_hf  [(size_t)Bc * Tn * C];
__device__ __align__(16) __nv_bfloat16 g_hhi [(size_t)Bc * Tn * C];
__device__ __align__(16) __nv_bfloat16 g_hlo [(size_t)Bc * Tn * C];
__device__ __align__(16) __nv_bfloat16 g_ghi [(size_t)Bc * Tn * C];
__device__ __align__(16) __nv_bfloat16 g_glo [(size_t)Bc * Tn * C];
__device__ float g_part[(size_t)NENC * Bc * 32 * C];   // per-layer per-tile gated col sums
__device__ float g_pooled[Bc * C];
__device__ float g_z[Bc * LATENT];

// ---------------- helpers ----------------
__device__ __forceinline__ uint32_t smem_u32(const void* p) {
    uint32_t a;
    asm("{ .reg .u64 t; cvta.to.shared.u64 t, %1; cvt.u32.u64 %0, t; }" : "=r"(a) : "l"(p));
    return a;
}
__device__ __forceinline__ uint32_t swz(uint32_t off) { return off ^ ((off >> 3) & 0x70); }
__device__ __forceinline__ void cp16(uint32_t dst, const void* src, int sz) {
    asm volatile("cp.async.cg.shared.global [%0], [%1], 16, %2;"
                 :: "r"(dst), "l"(src), "r"(sz) : "memory");
}
#define LDSM4(r, addr) \
    asm volatile("ldmatrix.sync.aligned.m8n8.x4.shared.b16 {%0,%1,%2,%3}, [%4];" \
                 : "=r"((r)[0]), "=r"((r)[1]), "=r"((r)[2]), "=r"((r)[3]) : "r"(addr))
#define MMA(c, a, b0r, b1r) \
    asm volatile("mma.sync.aligned.m16n8k16.row.col.f32.bf16.bf16.f32 " \
                 "{%0,%1,%2,%3}, {%4,%5,%6,%7}, {%8,%9}, {%0,%1,%2,%3};" \
                 : "+f"((c)[0]), "+f"((c)[1]), "+f"((c)[2]), "+f"((c)[3]) \
                 : "r"((a)[0]), "r"((a)[1]), "r"((a)[2]), "r"((a)[3]), "r"(b0r), "r"(b1r))

__device__ __forceinline__ void split2(float v, __nv_bfloat16& h, __nv_bfloat16& l) {
    h = __float2bfloat16(v);
    l = __float2bfloat16(v - __bfloat162float(h));
}
__device__ __forceinline__ uint32_t pack2(__nv_bfloat16 a, __nv_bfloat16 b) {
    return (uint32_t)__bfloat16_as_ushort(a) | ((uint32_t)__bfloat16_as_ushort(b) << 16);
}

// ---------------- weight pre-pack ----------------
// wp1: [layer][oh][chunk 8][ms 4: f_hi,f_lo,g_hi,g_lo][16384B]; chunk: tap=kc>>2, c0=(kc&3)*64
__global__ void prep1_kernel(const float* __restrict__ Wf, const float* __restrict__ Wg) {
    size_t idx = (size_t)blockIdx.x * 256 + threadIdx.x;   // 2,621,440
    int j2 = idx & 31;
    int r  = (idx >> 5) & 127;
    int kc = (idx >> 12) & 7;
    int oh = (idx >> 15) & 1;
    int l  = (int)(idx >> 16);
    int o = oh * 128 + r;
    int tap = kc >> 2;
    int c = (kc & 3) * 64 + j2 * 2;
    uint32_t boff = swz((uint32_t)(r * 128 + j2 * 4));
    unsigned char* base = g_wp1 + ((((size_t)(l * 2 + oh) * 8 + kc) * 4) << 14) + boff;
    const float* pf = Wf + (((size_t)l * C + o) * C + c) * 2 + tap;
    const float* pg = Wg + (((size_t)l * C + o) * C + c) * 2 + tap;
    __nv_bfloat16 h0, l0, h1, l1;
    split2(pf[0], h0, l0); split2(pf[2], h1, l1);
    *(uint32_t*)(base)             = pack2(h0, h1);
    *(uint32_t*)(base + 16384)     = pack2(l0, l1);
    split2(pg[0], h0, l0); split2(pg[2], h1, l1);
    *(uint32_t*)(base + 2 * 16384) = pack2(h0, h1);
    *(uint32_t*)(base + 3 * 16384) = pack2(l0, l1);
}
// wp2: [layer][oh][chunk 4][ms 2: r_hi,r_lo][16384B]
__global__ void prep2_kernel(const float* __restrict__ Wr) {
    size_t idx = (size_t)blockIdx.x * 256 + threadIdx.x;   // 1,310,720
    int j2 = idx & 31;
    int r  = (idx >> 5) & 127;
    int kc = (idx >> 12) & 3;
    int oh = (idx >> 14) & 1;
    int l  = (int)(idx >> 15);
    int o = oh * 128 + r;
    int c = kc * 64 + j2 * 2;
    uint32_t boff = swz((uint32_t)(r * 128 + j2 * 4));
    unsigned char* base = g_wp2 + ((((size_t)(l * 2 + oh) * 4 + kc) * 2) << 14) + boff;
    const float* pr = Wr + ((size_t)l * C + o) * C + c;
    __nv_bfloat16 h0, l0, h1, l1;
    split2(pr[0], h0, l0); split2(pr[1], h1, l1);
    *(uint32_t*)(base)         = pack2(h0, h1);
    *(uint32_t*)(base + 16384) = pack2(l0, l1);
}

// ---------------- encoder input conv ----------------
__global__ void enc_in_kernel(const float* __restrict__ x,
                              const float* __restrict__ W,
                              const float* __restrict__ bias) {
    size_t idx = (size_t)blockIdx.x * 256 + threadIdx.x;   // ((b*Tn+t)*C + c)
    int c = idx & 255;
    int t = (int)((idx >> 8) & 4095);
    int b = (int)(idx >> 20);
    float xc = x[b * Tn + t];
    float xp = (t > 0) ? x[b * Tn + t - 1] : 0.f;
    float h = W[c * 2] * xp + W[c * 2 + 1] * xc + bias[c];
    g_hf[idx] = h;
    __nv_bfloat16 hh, hl;
    split2(h, hh, hl);
    g_hhi[idx] = hh;
    g_hlo[idx] = hl;
}

// ---------------- unified bf16x3 mma.sync GEMM kernel ----------------
// mode 0: conv f/g (8 K-chunks, dilation), epilogue gates + col-sum partials.
// mode 1: res 1x1 (4 K-chunks), epilogue residual update.
// grid (Bc*32, 4), 512 threads. CTA: 128 t x 64 out-ch. 16 warps = wm4 x nw4;
// each warp computes BOTH matrices for its 32x16 tile (no exchange needed).
__global__ void __launch_bounds__(512, 1)
gemm_kernel(int layer, int dil, int mode,
            const float* __restrict__ b0_, const float* __restrict__ b1_) {
    extern __shared__ unsigned char sm[];
    uint32_t smb = smem_u32(sm);
    const int tid = threadIdx.x, wid = tid >> 5, lane = tid & 31;
    const int b = blockIdx.x >> 5, tile = blockIdx.x & 31;
    const int oh2 = blockIdx.y;
    const int t0 = tile * NT;
    const int cg0 = oh2 * 64, oh = oh2 >> 1, slice = oh2 & 1;
    const int nch = mode ? 4 : 8;
    const int nB = mode ? 1024 : 2048;
    const int nmat = mode ? 1 : 2;
    const int wm = wid & 3, nw = wid >> 2;

    const unsigned char* wbase = mode
        ? g_wp2 + ((size_t)(layer * 2 + oh) << 17)
        : g_wp1 + ((size_t)(layer * 2 + oh) << 19);
    const __nv_bfloat16* ahi = mode ? g_ghi : g_hhi;
    const __nv_bfloat16* alo = mode ? g_glo : g_hlo;

    auto load_chunk = [&](int kc, int s) {
        uint32_t stb = smb + (uint32_t)s * STAGE_BYTES;
        int toff = (!mode && (kc >> 2) == 0) ? dil : 0;
        int c0 = mode ? kc * 64 : (kc & 3) * 64;
        size_t kcs = mode ? ((size_t)kc << 15) : ((size_t)kc << 16);
        #pragma unroll
        for (int it = 0; it < 8; ++it) {
            int idx = it * 512 + tid;
            if (idx < 2048) {                        // A tiles hi/lo: 128 rows x 128B
                int sp = idx >> 10, seg = idx & 1023;
                int r = seg >> 3, j = seg & 7;
                int t = t0 + r - toff;
                int tc = t < 0 ? 0 : t;
                const __nv_bfloat16* s0 = sp ? alo : ahi;
                const char* src = (const char*)(s0 + ((size_t)b * Tn + tc) * C + c0) + j * 16;
                cp16(stb + sp * 16384 + swz((uint32_t)(r * 128 + j * 16)), src, t >= 0 ? 16 : 0);
            } else if (idx < 2048 + nB) {            // B weights, pre-swizzled, linear
                int bi = idx - 2048;
                int ms = bi >> 9, seg = bi & 511;
                const unsigned char* src = wbase + kcs + (size_t)ms * 16384
                                         + (size_t)slice * 8192 + (size_t)seg * 16;
                cp16(stb + 32768 + (uint32_t)bi * 16, src, 16);
            }
        }
        asm volatile("cp.async.commit_group;" ::: "memory");
    };

    load_chunk(0, 0);
    if (nch > 1) load_chunk(1, 1);

    float acc[2][2][2][4];
    #pragma unroll
    for (int m = 0; m < 2; ++m)
        #pragma unroll
        for (int mt = 0; mt < 2; ++mt)
            #pragma unroll
            for (int nt = 0; nt < 2; ++nt)
                #pragma unroll
                for (int q = 0; q < 4; ++q) acc[m][mt][nt][q] = 0.f;

    const int laneA_r = lane & 15, laneA_j = lane >> 4;
    const int laneB_r = ((lane >> 4) << 3) + (lane & 7), laneB_j = (lane >> 3) & 1;

    for (int i = 0; i < nch; ++i) {
        int s = i % NSTAGE;
        if (i + 1 < nch) asm volatile("cp.async.wait_group 1;" ::: "memory");
        else             asm volatile("cp.async.wait_group 0;" ::: "memory");
        __syncthreads();
        if (i + 2 < nch) load_chunk(i + 2, (i + 2) % NSTAGE);  // stage freed at i-1

        uint32_t stb = smb + (uint32_t)s * STAGE_BYTES;
        uint32_t aH = stb, aL = stb + 16384;
        #pragma unroll
        for (int ks = 0; ks < 4; ++ks) {
            uint32_t ah[2][4], al[2][4];
            #pragma unroll
            for (int mt = 0; mt < 2; ++mt) {
                uint32_t off = swz((uint32_t)((wm * 32 + mt * 16 + laneA_r) * 128
                                              + (ks * 2 + laneA_j) * 16));
                LDSM4(ah[mt], aH + off);
                LDSM4(al[mt], aL + off);
            }
            uint32_t offB = swz((uint32_t)((nw * 16 + laneB_r) * 128
                                           + (ks * 2 + laneB_j) * 16));
            #pragma unroll
            for (int m = 0; m < 2; ++m) {
                if (m >= nmat) break;
                uint32_t bB = stb + 32768 + (uint32_t)m * 16384;
                uint32_t bh[4], bl[4];
                LDSM4(bh, bB + offB);
                LDSM4(bl, bB + 8192 + offB);
                #pragma unroll
                for (int mt = 0; mt < 2; ++mt) {
                    MMA(acc[m][mt][0], ah[mt], bh[0], bh[1]);
                    MMA(acc[m][mt][1], ah[mt], bh[2], bh[3]);
                    MMA(acc[m][mt][0], al[mt], bh[0], bh[1]);
                    MMA(acc[m][mt][1], al[mt], bh[2], bh[3]);
                    MMA(acc[m][mt][0], ah[mt], bl[0], bl[1]);
                    MMA(acc[m][mt][1], ah[mt], bl[2], bl[3]);
                }
            }
        }
    }
    __syncthreads();   // all MMA smem reads done (also guards psum reuse of stage 0)

    // ---- fused register epilogue ----
    const int rbase = t0 + wm * 32 + (lane >> 2);
    const int cbase = cg0 + nw * 16 + (lane & 3) * 2;

    if (mode == 0) {
        float cs[2][2] = {{0.f, 0.f}, {0.f, 0.f}};
        #pragma unroll
        for (int mt = 0; mt < 2; ++mt)
            #pragma unroll
            for (int nt = 0; nt < 2; ++nt) {
                int c = cbase + nt * 8;
                float bf0 = b0_[c], bf1 = b0_[c + 1];
                float bg0 = b1_[c], bg1 = b1_[c + 1];
                #pragma unroll
                for (int hh = 0; hh < 2; ++hh) {
                    int t = rbase + mt * 16 + hh * 8;
                    float f0 = acc[0][mt][nt][2 * hh]     + bf0;
                    float f1 = acc[0][mt][nt][2 * hh + 1] + bf1;
                    float g0 = acc[1][mt][nt][2 * hh]     + bg0;
                    float g1 = acc[1][mt][nt][2 * hh + 1] + bg1;
                    float v0 = tanhf(f0) / (1.f + expf(-g0));
                    float v1 = tanhf(f1) / (1.f + expf(-g1));
                    __nv_bfloat16 h0, l0, h1, l1;
                    split2(v0, h0, l0); split2(v1, h1, l1);
                    size_t base = ((size_t)b * Tn + t) * C + c;
                    *(uint32_t*)(g_ghi + base) = pack2(h0, h1);
                    *(uint32_t*)(g_glo + base) = pack2(l0, l1);
                    cs[nt][0] += v0;
                    cs[nt][1] += v1;
                }
            }
        // reduce over the 8 lanes sharing the same column set (stride 4)
        #pragma unroll
        for (int nt = 0; nt < 2; ++nt)
            #pragma unroll
            for (int q = 0; q < 2; ++q) {
                cs[nt][q] += __shfl_down_sync(0xffffffffu, cs[nt][q], 16);
                cs[nt][q] += __shfl_down_sync(0xffffffffu, cs[nt][q], 8);
                cs[nt][q] += __shfl_down_sync(0xffffffffu, cs[nt][q], 4);
            }
        float* psum = (float*)sm;                  // [4 wm][64 cols]
        if (lane < 4) {
            #pragma unroll
            for (int nt = 0; nt < 2; ++nt) {
                int col = nw * 16 + nt * 8 + lane * 2;
                psum[wm * 64 + col]     = cs[nt][0];
                psum[wm * 64 + col + 1] = cs[nt][1];
            }
        }
        __syncthreads();
        if (tid < 64) {
            float s = psum[tid] + psum[64 + tid] + psum[128 + tid] + psum[192 + tid];
            g_part[(((size_t)layer * Bc + b) * 32 + tile) * C + cg0 + tid] = s;
        }
    } else {
        #pragma unroll
        for (int mt = 0; mt < 2; ++mt)
            #pragma unroll
            for (int nt = 0; nt < 2; ++nt) {
                int c = cbase + nt * 8;
                float br0 = b0_[c], br1 = b0_[c + 1];
                #pragma unroll
                for (int hh = 0; hh < 2; ++hh) {
                    int t = rbase + mt * 16 + hh * 8;
                    size_t base = ((size_t)b * Tn + t) * C + c;
                    float2 hv = *(float2*)(g_hf + base);
                    float n0 = acc[0][mt][nt][2 * hh]     + br0 + hv.x;
                    float n1 = acc[0][mt][nt][2 * hh + 1] + br1 + hv.y;
                    *(float2*)(g_hf + base) = make_float2(n0, n1);
                    __nv_bfloat16 h0, l0, h1, l1;
                    split2(n0, h0, l0); split2(n1, h1, l1);
                    *(uint32_t*)(g_hhi + base) = pack2(h0, h1);
                    *(uint32_t*)(g_hlo + base) = pack2(l0, l1);
                }
            }
    }
}

// ---------------- pooled: Σ_l [Ws_l @ mean_t(out_l)] + Σ_l bs_l ----------------
__global__ void pooled_kernel(const float* __restrict__ Ws, const float* __restrict__ bs) {
    __shared__ float smv[C];
    int b = blockIdx.x, c = threadIdx.x;   // 256 threads
    float aw = 0.f, ab = 0.f;
    for (int l = 0; l < NENC; ++l) {
        float s = 0.f;
        const float* p = g_part + (((size_t)l * Bc + b) * 32) * C + c;
        #pragma unroll 4
        for (int tile = 0; tile < 32; ++tile) s += p[(size_t)tile * C];
        __syncthreads();
        smv[c] = s;
        __syncthreads();
        const float4* w4 = (const float4*)(Ws + ((size_t)l * C + c) * C);
        const float4* s4 = (const float4*)smv;
        float a0 = 0.f;
        #pragma unroll 8
        for (int k = 0; k < 64; ++k) {
            float4 w = w4[k], v = s4[k];
            a0 += w.x * v.x + w.y * v.y + w.z * v.z + w.w * v.w;
        }
        aw += a0;
        ab += bs[l * C + c];
    }
    g_pooled[b * C + c] = aw * (1.f / Tn) + ab;
}

// ---------------- mu / logvar / reparameterize ----------------
__global__ void fc_kernel(const float* __restrict__ muW, const float* __restrict__ mub,
                          const float* __restrict__ lvW, const float* __restrict__ lvb,
                          const float* __restrict__ eps, float* __restrict__ out) {
    int b = blockIdx.x, l = threadIdx.x;
    const float* p = g_pooled + b * C;
    float m0 = mub[l], m1 = 0.f, v0 = lvb[l], v1 = 0.f;
    const float* wm = muW + l * C;
    const float* wv = lvW + l * C;
    for (int c = 0; c < C; c += 2) {
        m0 += wm[c] * p[c];     m1 += wm[c + 1] * p[c + 1];
        v0 += wv[c] * p[c];     v1 += wv[c + 1] * p[c + 1];
    }
    float mu = m0 + m1, lv = v0 + v1;
    out[4 + b * LATENT + l] = mu;
    out[4 + Bc * LATENT + b * LATENT + l] = lv;
    g_z[b * LATENT + l] = mu + eps[b * LATENT + l] * expf(0.5f * lv);
}

// ---------------- decoder (T=1: only tap 1 of each k=2 conv contributes) ----------------
__global__ void dec_kernel(const float* __restrict__ inW, const float* __restrict__ inb,
                           const float* __restrict__ Wf, const float* __restrict__ bf,
                           const float* __restrict__ Wg, const float* __restrict__ bg,
                           const float* __restrict__ Wr, const float* __restrict__ br,
                           const float* __restrict__ outW, const float* __restrict__ outb,
                           float* __restrict__ out) {
    __shared__ float h2[C], fg[C], red[C];
    int b = blockIdx.x, c = threadIdx.x;
    {
        float s = inb[c];
        const float* w = inW + c * LATENT;
        const float* zz = g_z + b * LATENT;
        for (int l = 0; l < LATENT; ++l) s += w[l] * zz[l];
        h2[c] = s;
    }
    __syncthreads();
    for (int i = 0; i < NDEC; ++i) {
        const float* wf = Wf + (size_t)(i * C + c) * C * 2;
        const float* wg = Wg + (size_t)(i * C + c) * C * 2;
        float f0 = bf[i * C + c], f1 = 0.f, g0 = bg[i * C + c], g1 = 0.f;
        for (int cc = 0; cc < C; cc += 2) {
            float h0 = h2[cc], h1 = h2[cc + 1];
            f0 += wf[cc * 2 + 1] * h0;  f1 += wf[cc * 2 + 3] * h1;
            g0 += wg[cc * 2 + 1] * h0;  g1 += wg[cc * 2 + 3] * h1;
        }
        float fv = f0 + f1, gv = g0 + g1;
        fg[c] = tanhf(fv) / (1.f + expf(-gv));
        __syncthreads();
        const float* wr = Wr + (size_t)(i * C + c) * C;
        float r0 = br[i * C + c], r1 = 0.f;
        for (int cc = 0; cc < C; cc += 2) {
            r0 += wr[cc] * fg[cc];
            r1 += wr[cc + 1] * fg[cc + 1];
        }
        h2[c] += r0 + r1;
        __syncthreads();
    }
    red[c] = outW[c] * h2[c];
    __syncthreads();
    for (int off = 128; off; off >>= 1) {
        if (c < off) red[c] += red[c + off];
        __syncthreads();
    }
    if (c == 0) out[b] = red[0] + outb[0];
}

// ---------------- host ----------------
extern "C" void kernel_launch(void* const* d_in, const int* in_sizes, int n_in,
                              void* d_out, int out_size) {
    const float* x        = (const float*)d_in[0];
    const float* eps      = (const float*)d_in[1];
    const float* enc_in_W = (const float*)d_in[2];
    const float* enc_in_b = (const float*)d_in[3];
    const float* enc_Wf   = (const float*)d_in[4];
    const float* enc_bf   = (const float*)d_in[5];
    const float* enc_Wg   = (const float*)d_in[6];
    const float* enc_bg   = (const float*)d_in[7];
    const float* enc_Wr   = (const float*)d_in[8];
    const float* enc_br   = (const float*)d_in[9];
    const float* enc_Ws   = (const float*)d_in[10];
    const float* enc_bs   = (const float*)d_in[11];
    const float* fc_mu_W  = (const float*)d_in[12];
    const float* fc_mu_b  = (const float*)d_in[13];
    const float* fc_lv_W  = (const float*)d_in[14];
    const float* fc_lv_b  = (const float*)d_in[15];
    const float* dec_in_W = (const float*)d_in[16];
    const float* dec_in_b = (const float*)d_in[17];
    const float* dec_Wf   = (const float*)d_in[18];
    const float* dec_bf   = (const float*)d_in[19];
    const float* dec_Wg   = (const float*)d_in[20];
    const float* dec_bg   = (const float*)d_in[21];
    const float* dec_Wr   = (const float*)d_in[22];
    const float* dec_br   = (const float*)d_in[23];
    const float* out_W    = (const float*)d_in[24];
    const float* out_b    = (const float*)d_in[25];
    float* out = (float*)d_out;

    cudaFuncSetAttribute(gemm_kernel, cudaFuncAttributeMaxDynamicSharedMemorySize, SMEM_TOTAL);

    prep1_kernel<<<10240, 256>>>(enc_Wf, enc_Wg);
    prep2_kernel<<<5120, 256>>>(enc_Wr);
    enc_in_kernel<<<(Bc * Tn * C) / 256, 256>>>(x, enc_in_W, enc_in_b);

    for (int i = 0; i < NENC; ++i) {
        int dil = 1 << (i % 10);
        gemm_kernel<<<dim3(Bc * 32, 4), 512, SMEM_TOTAL>>>(i, dil, 0,
                                                           enc_bf + i * C, enc_bg + i * C);
        gemm_kernel<<<dim3(Bc * 32, 4), 512, SMEM_TOTAL>>>(i, 0, 1,
                                                           enc_br + i * C, (const float*)0);
    }

    pooled_kernel<<<Bc, 256>>>(enc_Ws, enc_bs);
    fc_kernel<<<Bc, LATENT>>>(fc_mu_W, fc_mu_b, fc_lv_W, fc_lv_b, eps, out);
    dec_kernel<<<Bc, C>>>(dec_in_W, dec_in_b, dec_Wf, dec_bf, dec_Wg, dec_bg,
                          dec_Wr, dec_br, out_W, out_b, out);
}

// round 10
// speedup vs baseline: 4.2372x; 1.1820x over previous
#include <cuda_runtime.h>
#include <cuda_bf16.h>
#include <math.h>
#include <stdint.h>

#define Bc 4
#define C 256
#define Tn 4096
#define LATENT 128
#define NENC 40
#define NDEC 10
#define NT 128

#define STAGE_BYTES 65536
#define NSTAGE 3
#define SMEM_TOTAL (NSTAGE * STAGE_BYTES)

// ---------------- device scratch ----------------
__device__ __align__(16) unsigned char g_wp1[(size_t)NENC * 2 * 8 * 4 * 16384]; // 40MB
__device__ __align__(16) unsigned char g_wp2[(size_t)NENC * 2 * 4 * 2 * 16384]; // 10MB
__device__ __align__(16) float         g_hf  [(size_t)Bc * Tn * C];
__device__ __align__(16) __nv_bfloat16 g_hhi [(size_t)Bc * Tn * C];
__device__ __align__(16) __nv_bfloat16 g_hlo [(size_t)Bc * Tn * C];
__device__ __align__(16) __nv_bfloat16 g_ghi [(size_t)Bc * Tn * C];
__device__ __align__(16) __nv_bfloat16 g_glo [(size_t)Bc * Tn * C];
__device__ float g_part[(size_t)NENC * Bc * 32 * C];   // per-layer per-tile gated col sums
__device__ float g_m[NENC * Bc * C];                   // per-layer time-sums
__device__ float g_pooled[Bc * C];
__device__ float g_z[Bc * LATENT];
// transposed small weights (coalesced access)
__device__ float g_dwfT[NDEC * C * C], g_dwgT[NDEC * C * C], g_dwrT[NDEC * C * C];
__device__ float g_dinT[LATENT * C];
__device__ float g_fmuT[C * LATENT], g_flvT[C * LATENT];

// ---------------- helpers ----------------
__device__ __forceinline__ uint32_t smem_u32(const void* p) {
    uint32_t a;
    asm("{ .reg .u64 t; cvta.to.shared.u64 t, %1; cvt.u32.u64 %0, t; }" : "=r"(a) : "l"(p));
    return a;
}
__device__ __forceinline__ uint32_t swz(uint32_t off) { return off ^ ((off >> 3) & 0x70); }
__device__ __forceinline__ void cp16(uint32_t dst, const void* src, int sz) {
    asm volatile("cp.async.cg.shared.global [%0], [%1], 16, %2;"
                 :: "r"(dst), "l"(src), "r"(sz) : "memory");
}
#define LDSM4(r, addr) \
    asm volatile("ldmatrix.sync.aligned.m8n8.x4.shared.b16 {%0,%1,%2,%3}, [%4];" \
                 : "=r"((r)[0]), "=r"((r)[1]), "=r"((r)[2]), "=r"((r)[3]) : "r"(addr))
#define MMA(c, a, b0r, b1r) \
    asm volatile("mma.sync.aligned.m16n8k16.row.col.f32.bf16.bf16.f32 " \
                 "{%0,%1,%2,%3}, {%4,%5,%6,%7}, {%8,%9}, {%0,%1,%2,%3};" \
                 : "+f"((c)[0]), "+f"((c)[1]), "+f"((c)[2]), "+f"((c)[3]) \
                 : "r"((a)[0]), "r"((a)[1]), "r"((a)[2]), "r"((a)[3]), "r"(b0r), "r"(b1r))

__device__ __forceinline__ void split2(float v, __nv_bfloat16& h, __nv_bfloat16& l) {
    h = __float2bfloat16(v);
    l = __float2bfloat16(v - __bfloat162float(h));
}
__device__ __forceinline__ uint32_t pack2(__nv_bfloat16 a, __nv_bfloat16 b) {
    return (uint32_t)__bfloat16_as_ushort(a) | ((uint32_t)__bfloat16_as_ushort(b) << 16);
}

// ---------------- weight pre-pack ----------------
__global__ void prep1_kernel(const float* __restrict__ Wf, const float* __restrict__ Wg) {
    size_t idx = (size_t)blockIdx.x * 256 + threadIdx.x;   // 2,621,440
    int j2 = idx & 31;
    int r  = (idx >> 5) & 127;
    int kc = (idx >> 12) & 7;
    int oh = (idx >> 15) & 1;
    int l  = (int)(idx >> 16);
    int o = oh * 128 + r;
    int tap = kc >> 2;
    int c = (kc & 3) * 64 + j2 * 2;
    uint32_t boff = swz((uint32_t)(r * 128 + j2 * 4));
    unsigned char* base = g_wp1 + ((((size_t)(l * 2 + oh) * 8 + kc) * 4) << 14) + boff;
    const float* pf = Wf + (((size_t)l * C + o) * C + c) * 2 + tap;
    const float* pg = Wg + (((size_t)l * C + o) * C + c) * 2 + tap;
    __nv_bfloat16 h0, l0, h1, l1;
    split2(pf[0], h0, l0); split2(pf[2], h1, l1);
    *(uint32_t*)(base)             = pack2(h0, h1);
    *(uint32_t*)(base + 16384)     = pack2(l0, l1);
    split2(pg[0], h0, l0); split2(pg[2], h1, l1);
    *(uint32_t*)(base + 2 * 16384) = pack2(h0, h1);
    *(uint32_t*)(base + 3 * 16384) = pack2(l0, l1);
}
__global__ void prep2_kernel(const float* __restrict__ Wr) {
    size_t idx = (size_t)blockIdx.x * 256 + threadIdx.x;   // 1,310,720
    int j2 = idx & 31;
    int r  = (idx >> 5) & 127;
    int kc = (idx >> 12) & 3;
    int oh = (idx >> 14) & 1;
    int l  = (int)(idx >> 15);
    int o = oh * 128 + r;
    int c = kc * 64 + j2 * 2;
    uint32_t boff = swz((uint32_t)(r * 128 + j2 * 4));
    unsigned char* base = g_wp2 + ((((size_t)(l * 2 + oh) * 4 + kc) * 2) << 14) + boff;
    const float* pr = Wr + ((size_t)l * C + o) * C + c;
    __nv_bfloat16 h0, l0, h1, l1;
    split2(pr[0], h0, l0); split2(pr[1], h1, l1);
    *(uint32_t*)(base)         = pack2(h0, h1);
    *(uint32_t*)(base + 16384) = pack2(l0, l1);
}
// transpose small dense weights for coalesced tail kernels
__global__ void prep3_kernel(const float* __restrict__ dWf, const float* __restrict__ dWg,
                             const float* __restrict__ dWr, const float* __restrict__ dinW,
                             const float* __restrict__ muW, const float* __restrict__ lvW) {
    int idx = blockIdx.x * 256 + threadIdx.x;    // 2560 blocks -> 655360
    if (idx < NDEC * C * C) {
        int o = idx & 255, cc = (idx >> 8) & 255, l = idx >> 16;
        g_dwfT[idx] = dWf[(((size_t)l * C + o) * C + cc) * 2 + 1];
        g_dwgT[idx] = dWg[(((size_t)l * C + o) * C + cc) * 2 + 1];
        g_dwrT[idx] = dWr[((size_t)l * C + o) * C + cc];
    }
    if (idx < LATENT * C) {                      // dinT[l][o]
        int o = idx & 255, l = idx >> 8;
        g_dinT[idx] = dinW[o * LATENT + l];
    }
    if (idx < C * LATENT) {                      // fmuT[c][l]
        int l = idx & 127, c = idx >> 7;
        g_fmuT[idx] = muW[l * C + c];
        g_flvT[idx] = lvW[l * C + c];
    }
}

// ---------------- encoder input conv ----------------
__global__ void enc_in_kernel(const float* __restrict__ x,
                              const float* __restrict__ W,
                              const float* __restrict__ bias) {
    size_t idx = (size_t)blockIdx.x * 256 + threadIdx.x;   // ((b*Tn+t)*C + c)
    int c = idx & 255;
    int t = (int)((idx >> 8) & 4095);
    int b = (int)(idx >> 20);
    float xc = x[b * Tn + t];
    float xp = (t > 0) ? x[b * Tn + t - 1] : 0.f;
    float h = W[c * 2] * xp + W[c * 2 + 1] * xc + bias[c];
    g_hf[idx] = h;
    __nv_bfloat16 hh, hl;
    split2(h, hh, hl);
    g_hhi[idx] = hh;
    g_hlo[idx] = hl;
}

// ---------------- unified bf16x3 mma.sync GEMM kernel (unchanged from R9) ----------------
__global__ void __launch_bounds__(512, 1)
gemm_kernel(int layer, int dil, int mode,
            const float* __restrict__ b0_, const float* __restrict__ b1_) {
    extern __shared__ unsigned char sm[];
    uint32_t smb = smem_u32(sm);
    const int tid = threadIdx.x, wid = tid >> 5, lane = tid & 31;
    const int b = blockIdx.x >> 5, tile = blockIdx.x & 31;
    const int oh2 = blockIdx.y;
    const int t0 = tile * NT;
    const int cg0 = oh2 * 64, oh = oh2 >> 1, slice = oh2 & 1;
    const int nch = mode ? 4 : 8;
    const int nB = mode ? 1024 : 2048;
    const int nmat = mode ? 1 : 2;
    const int wm = wid & 3, nw = wid >> 2;

    const unsigned char* wbase = mode
        ? g_wp2 + ((size_t)(layer * 2 + oh) << 17)
        : g_wp1 + ((size_t)(layer * 2 + oh) << 19);
    const __nv_bfloat16* ahi = mode ? g_ghi : g_hhi;
    const __nv_bfloat16* alo = mode ? g_glo : g_hlo;

    auto load_chunk = [&](int kc, int s) {
        uint32_t stb = smb + (uint32_t)s * STAGE_BYTES;
        int toff = (!mode && (kc >> 2) == 0) ? dil : 0;
        int c0 = mode ? kc * 64 : (kc & 3) * 64;
        size_t kcs = mode ? ((size_t)kc << 15) : ((size_t)kc << 16);
        #pragma unroll
        for (int it = 0; it < 8; ++it) {
            int idx = it * 512 + tid;
            if (idx < 2048) {
                int sp = idx >> 10, seg = idx & 1023;
                int r = seg >> 3, j = seg & 7;
                int t = t0 + r - toff;
                int tc = t < 0 ? 0 : t;
                const __nv_bfloat16* s0 = sp ? alo : ahi;
                const char* src = (const char*)(s0 + ((size_t)b * Tn + tc) * C + c0) + j * 16;
                cp16(stb + sp * 16384 + swz((uint32_t)(r * 128 + j * 16)), src, t >= 0 ? 16 : 0);
            } else if (idx < 2048 + nB) {
                int bi = idx - 2048;
                int ms = bi >> 9, seg = bi & 511;
                const unsigned char* src = wbase + kcs + (size_t)ms * 16384
                                         + (size_t)slice * 8192 + (size_t)seg * 16;
                cp16(stb + 32768 + (uint32_t)bi * 16, src, 16);
            }
        }
        asm volatile("cp.async.commit_group;" ::: "memory");
    };

    load_chunk(0, 0);
    if (nch > 1) load_chunk(1, 1);

    float acc[2][2][2][4];
    #pragma unroll
    for (int m = 0; m < 2; ++m)
        #pragma unroll
        for (int mt = 0; mt < 2; ++mt)
            #pragma unroll
            for (int nt = 0; nt < 2; ++nt)
                #pragma unroll
                for (int q = 0; q < 4; ++q) acc[m][mt][nt][q] = 0.f;

    const int laneA_r = lane & 15, laneA_j = lane >> 4;
    const int laneB_r = ((lane >> 4) << 3) + (lane & 7), laneB_j = (lane >> 3) & 1;

    for (int i = 0; i < nch; ++i) {
        int s = i % NSTAGE;
        if (i + 1 < nch) asm volatile("cp.async.wait_group 1;" ::: "memory");
        else             asm volatile("cp.async.wait_group 0;" ::: "memory");
        __syncthreads();
        if (i + 2 < nch) load_chunk(i + 2, (i + 2) % NSTAGE);

        uint32_t stb = smb + (uint32_t)s * STAGE_BYTES;
        uint32_t aH = stb, aL = stb + 16384;
        #pragma unroll
        for (int ks = 0; ks < 4; ++ks) {
            uint32_t ah[2][4], al[2][4];
            #pragma unroll
            for (int mt = 0; mt < 2; ++mt) {
                uint32_t off = swz((uint32_t)((wm * 32 + mt * 16 + laneA_r) * 128
                                              + (ks * 2 + laneA_j) * 16));
                LDSM4(ah[mt], aH + off);
                LDSM4(al[mt], aL + off);
            }
            uint32_t offB = swz((uint32_t)((nw * 16 + laneB_r) * 128
                                           + (ks * 2 + laneB_j) * 16));
            #pragma unroll
            for (int m = 0; m < 2; ++m) {
                if (m >= nmat) break;
                uint32_t bB = stb + 32768 + (uint32_t)m * 16384;
                uint32_t bh[4], bl[4];
                LDSM4(bh, bB + offB);
                LDSM4(bl, bB + 8192 + offB);
                #pragma unroll
                for (int mt = 0; mt < 2; ++mt) {
                    MMA(acc[m][mt][0], ah[mt], bh[0], bh[1]);
                    MMA(acc[m][mt][1], ah[mt], bh[2], bh[3]);
                    MMA(acc[m][mt][0], al[mt], bh[0], bh[1]);
                    MMA(acc[m][mt][1], al[mt], bh[2], bh[3]);
                    MMA(acc[m][mt][0], ah[mt], bl[0], bl[1]);
                    MMA(acc[m][mt][1], ah[mt], bl[2], bl[3]);
                }
            }
        }
    }
    __syncthreads();

    const int rbase = t0 + wm * 32 + (lane >> 2);
    const int cbase = cg0 + nw * 16 + (lane & 3) * 2;

    if (mode == 0) {
        float cs[2][2] = {{0.f, 0.f}, {0.f, 0.f}};
        #pragma unroll
        for (int mt = 0; mt < 2; ++mt)
            #pragma unroll
            for (int nt = 0; nt < 2; ++nt) {
                int c = cbase + nt * 8;
                float bf0 = b0_[c], bf1 = b0_[c + 1];
                float bg0 = b1_[c], bg1 = b1_[c + 1];
                #pragma unroll
                for (int hh = 0; hh < 2; ++hh) {
                    int t = rbase + mt * 16 + hh * 8;
                    float f0 = acc[0][mt][nt][2 * hh]     + bf0;
                    float f1 = acc[0][mt][nt][2 * hh + 1] + bf1;
                    float g0 = acc[1][mt][nt][2 * hh]     + bg0;
                    float g1 = acc[1][mt][nt][2 * hh + 1] + bg1;
                    float v0 = tanhf(f0) / (1.f + expf(-g0));
                    float v1 = tanhf(f1) / (1.f + expf(-g1));
                    __nv_bfloat16 h0, l0, h1, l1;
                    split2(v0, h0, l0); split2(v1, h1, l1);
                    size_t base = ((size_t)b * Tn + t) * C + c;
                    *(uint32_t*)(g_ghi + base) = pack2(h0, h1);
                    *(uint32_t*)(g_glo + base) = pack2(l0, l1);
                    cs[nt][0] += v0;
                    cs[nt][1] += v1;
                }
            }
        #pragma unroll
        for (int nt = 0; nt < 2; ++nt)
            #pragma unroll
            for (int q = 0; q < 2; ++q) {
                cs[nt][q] += __shfl_down_sync(0xffffffffu, cs[nt][q], 16);
                cs[nt][q] += __shfl_down_sync(0xffffffffu, cs[nt][q], 8);
                cs[nt][q] += __shfl_down_sync(0xffffffffu, cs[nt][q], 4);
            }
        float* psum = (float*)sm;
        if (lane < 4) {
            #pragma unroll
            for (int nt = 0; nt < 2; ++nt) {
                int col = nw * 16 + nt * 8 + lane * 2;
                psum[wm * 64 + col]     = cs[nt][0];
                psum[wm * 64 + col + 1] = cs[nt][1];
            }
        }
        __syncthreads();
        if (tid < 64) {
            float s = psum[tid] + psum[64 + tid] + psum[128 + tid] + psum[192 + tid];
            g_part[(((size_t)layer * Bc + b) * 32 + tile) * C + cg0 + tid] = s;
        }
    } else {
        #pragma unroll
        for (int mt = 0; mt < 2; ++mt)
            #pragma unroll
            for (int nt = 0; nt < 2; ++nt) {
                int c = cbase + nt * 8;
                float br0 = b0_[c], br1 = b0_[c + 1];
                #pragma unroll
                for (int hh = 0; hh < 2; ++hh) {
                    int t = rbase + mt * 16 + hh * 8;
                    size_t base = ((size_t)b * Tn + t) * C + c;
                    float2 hv = *(float2*)(g_hf + base);
                    float n0 = acc[0][mt][nt][2 * hh]     + br0 + hv.x;
                    float n1 = acc[0][mt][nt][2 * hh + 1] + br1 + hv.y;
                    *(float2*)(g_hf + base) = make_float2(n0, n1);
                    __nv_bfloat16 h0, l0, h1, l1;
                    split2(n0, h0, l0); split2(n1, h1, l1);
                    *(uint32_t*)(g_hhi + base) = pack2(h0, h1);
                    *(uint32_t*)(g_hlo + base) = pack2(l0, l1);
                }
            }
    }
}

// ---------------- pooled tail: tile reduce, then warp-per-channel GEMV ----------------
__global__ void pool_reduce_kernel() {        // grid NENC*Bc, 256 thr
    int lb = blockIdx.x;
    int c = threadIdx.x;
    const float* p = g_part + ((size_t)lb * 32) * C + c;
    float s = 0.f;
    #pragma unroll 8
    for (int t = 0; t < 32; ++t) s += p[(size_t)t * C];
    g_m[lb * C + c] = s;
}
__global__ void pooled_gemv_kernel(const float* __restrict__ Ws, const float* __restrict__ bs) {
    __shared__ float smm[NENC * C];           // 40KB
    int b = blockIdx.x, cg = blockIdx.y;      // grid (Bc, 32)
    int tid = threadIdx.x, w = tid >> 5, lane = tid & 31;
    for (int i = tid; i < NENC * C; i += 256) {
        int l = i >> 8, k = i & 255;
        smm[i] = g_m[(l * Bc + b) * C + k];
    }
    __syncthreads();
    int c = cg * 8 + w;                       // warp per output channel
    float a = 0.f;
    for (int l = 0; l < NENC; ++l) {
        const float* wrow = Ws + ((size_t)l * C + c) * C;
        const float* mrow = smm + l * C;
        #pragma unroll
        for (int k = lane; k < C; k += 32) a += wrow[k] * mrow[k];
    }
    a += __shfl_down_sync(0xffffffffu, a, 16);
    a += __shfl_down_sync(0xffffffffu, a, 8);
    a += __shfl_down_sync(0xffffffffu, a, 4);
    a += __shfl_down_sync(0xffffffffu, a, 2);
    a += __shfl_down_sync(0xffffffffu, a, 1);
    if (lane == 0) {
        float ab = 0.f;
        for (int l = 0; l < NENC; ++l) ab += bs[l * C + c];
        g_pooled[b * C + c] = a * (1.f / Tn) + ab;
    }
}

// ---------------- mu / logvar / reparameterize (coalesced transposed weights) ----------------
__global__ void fc_kernel(const float* __restrict__ mub, const float* __restrict__ lvb,
                          const float* __restrict__ eps, float* __restrict__ out) {
    int b = blockIdx.x, l = threadIdx.x;
    const float* p = g_pooled + b * C;
    float m0 = mub[l], v0 = lvb[l];
    for (int c = 0; c < C; ++c) {
        float pv = p[c];
        m0 += g_fmuT[c * LATENT + l] * pv;
        v0 += g_flvT[c * LATENT + l] * pv;
    }
    out[4 + b * LATENT + l] = m0;
    out[4 + Bc * LATENT + b * LATENT + l] = v0;
    g_z[b * LATENT + l] = m0 + eps[b * LATENT + l] * expf(0.5f * v0);
}

// ---------------- decoder (transposed weights, coalesced) ----------------
__global__ void dec_kernel(const float* __restrict__ inb,
                           const float* __restrict__ bf, const float* __restrict__ bg,
                           const float* __restrict__ br,
                           const float* __restrict__ outW, const float* __restrict__ outb,
                           float* __restrict__ out) {
    __shared__ float h2[C], fg[C], red[C];
    int b = blockIdx.x, c = threadIdx.x;
    {
        float s = inb[c];
        const float* zz = g_z + b * LATENT;
        #pragma unroll 4
        for (int l = 0; l < LATENT; ++l) s += g_dinT[l * C + c] * zz[l];
        h2[c] = s;
    }
    __syncthreads();
    for (int i = 0; i < NDEC; ++i) {
        float f = bf[i * C + c], g = bg[i * C + c];
        const float* wf = g_dwfT + (size_t)i * C * C;
        const float* wg = g_dwgT + (size_t)i * C * C;
        #pragma unroll 4
        for (int cc = 0; cc < C; ++cc) {
            float h = h2[cc];
            f += wf[cc * C + c] * h;
            g += wg[cc * C + c] * h;
        }
        fg[c] = tanhf(f) / (1.f + expf(-g));
        __syncthreads();
        float r = br[i * C + c];
        const float* wr = g_dwrT + (size_t)i * C * C;
        #pragma unroll 4
        for (int cc = 0; cc < C; ++cc) r += wr[cc * C + c] * fg[cc];
        h2[c] += r;
        __syncthreads();
    }
    red[c] = outW[c] * h2[c];
    __syncthreads();
    for (int off = 128; off; off >>= 1) {
        if (c < off) red[c] += red[c + off];
        __syncthreads();
    }
    if (c == 0) out[b] = red[0] + outb[0];
}

// ---------------- host ----------------
extern "C" void kernel_launch(void* const* d_in, const int* in_sizes, int n_in,
                              void* d_out, int out_size) {
    const float* x        = (const float*)d_in[0];
    const float* eps      = (const float*)d_in[1];
    const float* enc_in_W = (const float*)d_in[2];
    const float* enc_in_b = (const float*)d_in[3];
    const float* enc_Wf   = (const float*)d_in[4];
    const float* enc_bf   = (const float*)d_in[5];
    const float* enc_Wg   = (const float*)d_in[6];
    const float* enc_bg   = (const float*)d_in[7];
    const float* enc_Wr   = (const float*)d_in[8];
    const float* enc_br   = (const float*)d_in[9];
    const float* enc_Ws   = (const float*)d_in[10];
    const float* enc_bs   = (const float*)d_in[11];
    const float* fc_mu_W  = (const float*)d_in[12];
    const float* fc_mu_b  = (const float*)d_in[13];
    const float* fc_lv_W  = (const float*)d_in[14];
    const float* fc_lv_b  = (const float*)d_in[15];
    const float* dec_in_W = (const float*)d_in[16];
    const float* dec_in_b = (const float*)d_in[17];
    const float* dec_Wf   = (const float*)d_in[18];
    const float* dec_bf   = (const float*)d_in[19];
    const float* dec_Wg   = (const float*)d_in[20];
    const float* dec_bg   = (const float*)d_in[21];
    const float* dec_Wr   = (const float*)d_in[22];
    const float* dec_br   = (const float*)d_in[23];
    const float* out_W    = (const float*)d_in[24];
    const float* out_b    = (const float*)d_in[25];
    float* out = (float*)d_out;

    cudaFuncSetAttribute(gemm_kernel, cudaFuncAttributeMaxDynamicSharedMemorySize, SMEM_TOTAL);

    prep1_kernel<<<10240, 256>>>(enc_Wf, enc_Wg);
    prep2_kernel<<<5120, 256>>>(enc_Wr);
    prep3_kernel<<<2560, 256>>>(dec_Wf, dec_Wg, dec_Wr, dec_in_W, fc_mu_W, fc_lv_W);
    enc_in_kernel<<<(Bc * Tn * C) / 256, 256>>>(x, enc_in_W, enc_in_b);

    for (int i = 0; i < NENC; ++i) {
        int dil = 1 << (i % 10);
        gemm_kernel<<<dim3(Bc * 32, 4), 512, SMEM_TOTAL>>>(i, dil, 0,
                                                           enc_bf + i * C, enc_bg + i * C);
        gemm_kernel<<<dim3(Bc * 32, 4), 512, SMEM_TOTAL>>>(i, 0, 1,
                                                           enc_br + i * C, (const float*)0);
    }

    pool_reduce_kernel<<<NENC * Bc, 256>>>();
    pooled_gemv_kernel<<<dim3(Bc, 32), 256>>>(enc_Ws, enc_bs);
    fc_kernel<<<Bc, LATENT>>>(fc_mu_b, fc_lv_b, eps, out);
    dec_kernel<<<Bc, C>>>(dec_in_b, dec_bf, dec_bg, dec_br, out_W, out_b, out);
}

// round 12
// speedup vs baseline: 5.3481x; 1.2622x over previous
#include <cuda_runtime.h>
#include <cuda_fp16.h>
#include <math.h>
#include <stdint.h>

#define Bc 4
#define C 256
#define Tn 4096
#define LATENT 128
#define NENC 40
#define NDEC 10
#define NT 128

#define STAGE_BYTES 49152      // A 16K + B up to 32K
#define NSTAGE 3
#define SMEM_TOTAL (NSTAGE * STAGE_BYTES)

// ---------------- device scratch ----------------
__device__ __align__(16) unsigned char g_wp1[(size_t)NENC * 2 * 8 * 4 * 16384]; // 40MB
__device__ __align__(16) unsigned char g_wp2[(size_t)NENC * 2 * 4 * 2 * 16384]; // 10MB
__device__ __align__(16) float  g_hf  [(size_t)Bc * Tn * C];
__device__ __align__(16) __half g_hbf [(size_t)Bc * Tn * C];
__device__ __align__(16) __half g_gbf [(size_t)Bc * Tn * C];
__device__ float g_part[(size_t)NENC * Bc * 32 * C];   // per-layer per-tile gated col sums
__device__ float g_m[NENC * Bc * C];                   // per-layer time-sums
__device__ float g_pooled[Bc * C];
__device__ float g_z[Bc * LATENT];
// transposed small weights (coalesced access)
__device__ float g_dwfT[NDEC * C * C], g_dwgT[NDEC * C * C], g_dwrT[NDEC * C * C];
__device__ float g_dinT[LATENT * C];
__device__ float g_fmuT[C * LATENT], g_flvT[C * LATENT];

// ---------------- helpers ----------------
__device__ __forceinline__ uint32_t smem_u32(const void* p) {
    uint32_t a;
    asm("{ .reg .u64 t; cvta.to.shared.u64 t, %1; cvt.u32.u64 %0, t; }" : "=r"(a) : "l"(p));
    return a;
}
__device__ __forceinline__ uint32_t swz(uint32_t off) { return off ^ ((off >> 3) & 0x70); }
__device__ __forceinline__ void cp16(uint32_t dst, const void* src, int sz) {
    asm volatile("cp.async.cg.shared.global [%0], [%1], 16, %2;"
                 :: "r"(dst), "l"(src), "r"(sz) : "memory");
}
#define LDSM4(r, addr) \
    asm volatile("ldmatrix.sync.aligned.m8n8.x4.shared.b16 {%0,%1,%2,%3}, [%4];" \
                 : "=r"((r)[0]), "=r"((r)[1]), "=r"((r)[2]), "=r"((r)[3]) : "r"(addr))
#define MMA(c, a, b0r, b1r) \
    asm volatile("mma.sync.aligned.m16n8k16.row.col.f32.f16.f16.f32 " \
                 "{%0,%1,%2,%3}, {%4,%5,%6,%7}, {%8,%9}, {%0,%1,%2,%3};" \
                 : "+f"((c)[0]), "+f"((c)[1]), "+f"((c)[2]), "+f"((c)[3]) \
                 : "r"((a)[0]), "r"((a)[1]), "r"((a)[2]), "r"((a)[3]), "r"(b0r), "r"(b1r))

__device__ __forceinline__ void split2(float v, __half& h, __half& l) {
    h = __float2half(v);
    l = __float2half(v - __half2float(h));
}
__device__ __forceinline__ uint32_t pack2(__half a, __half b) {
    return (uint32_t)__half_as_ushort(a) | ((uint32_t)__half_as_ushort(b) << 16);
}

// ---------------- weight pre-pack: fp16 hi/lo (effective ~2^-22 systematic) ----------------
__global__ void prep1_kernel(const float* __restrict__ Wf, const float* __restrict__ Wg) {
    size_t idx = (size_t)blockIdx.x * 256 + threadIdx.x;   // 2,621,440
    int j2 = idx & 31;
    int r  = (idx >> 5) & 127;
    int kc = (idx >> 12) & 7;
    int oh = (idx >> 15) & 1;
    int l  = (int)(idx >> 16);
    int o = oh * 128 + r;
    int tap = kc >> 2;
    int c = (kc & 3) * 64 + j2 * 2;
    uint32_t boff = swz((uint32_t)(r * 128 + j2 * 4));
    unsigned char* base = g_wp1 + ((((size_t)(l * 2 + oh) * 8 + kc) * 4) << 14) + boff;
    const float* pf = Wf + (((size_t)l * C + o) * C + c) * 2 + tap;
    const float* pg = Wg + (((size_t)l * C + o) * C + c) * 2 + tap;
    __half h0, l0, h1, l1;
    split2(pf[0], h0, l0); split2(pf[2], h1, l1);
    *(uint32_t*)(base)             = pack2(h0, h1);
    *(uint32_t*)(base + 16384)     = pack2(l0, l1);
    split2(pg[0], h0, l0); split2(pg[2], h1, l1);
    *(uint32_t*)(base + 2 * 16384) = pack2(h0, h1);
    *(uint32_t*)(base + 3 * 16384) = pack2(l0, l1);
}
__global__ void prep2_kernel(const float* __restrict__ Wr) {
    size_t idx = (size_t)blockIdx.x * 256 + threadIdx.x;   // 1,310,720
    int j2 = idx & 31;
    int r  = (idx >> 5) & 127;
    int kc = (idx >> 12) & 3;
    int oh = (idx >> 14) & 1;
    int l  = (int)(idx >> 15);
    int o = oh * 128 + r;
    int c = kc * 64 + j2 * 2;
    uint32_t boff = swz((uint32_t)(r * 128 + j2 * 4));
    unsigned char* base = g_wp2 + ((((size_t)(l * 2 + oh) * 4 + kc) * 2) << 14) + boff;
    const float* pr = Wr + ((size_t)l * C + o) * C + c;
    __half h0, l0, h1, l1;
    split2(pr[0], h0, l0); split2(pr[1], h1, l1);
    *(uint32_t*)(base)         = pack2(h0, h1);
    *(uint32_t*)(base + 16384) = pack2(l0, l1);
}
// transpose small dense weights for coalesced tail kernels
__global__ void prep3_kernel(const float* __restrict__ dWf, const float* __restrict__ dWg,
                             const float* __restrict__ dWr, const float* __restrict__ dinW,
                             const float* __restrict__ muW, const float* __restrict__ lvW) {
    int idx = blockIdx.x * 256 + threadIdx.x;    // 2560 blocks -> 655360
    if (idx < NDEC * C * C) {
        int o = idx & 255, cc = (idx >> 8) & 255, l = idx >> 16;
        g_dwfT[idx] = dWf[(((size_t)l * C + o) * C + cc) * 2 + 1];
        g_dwgT[idx] = dWg[(((size_t)l * C + o) * C + cc) * 2 + 1];
        g_dwrT[idx] = dWr[((size_t)l * C + o) * C + cc];
    }
    if (idx < LATENT * C) {
        int o = idx & 255, l = idx >> 8;
        g_dinT[idx] = dinW[o * LATENT + l];
    }
    if (idx < C * LATENT) {
        int l = idx & 127, c = idx >> 7;
        g_fmuT[idx] = muW[l * C + c];
        g_flvT[idx] = lvW[l * C + c];
    }
}

// ---------------- encoder input conv ----------------
__global__ void enc_in_kernel(const float* __restrict__ x,
                              const float* __restrict__ W,
                              const float* __restrict__ bias) {
    size_t idx = (size_t)blockIdx.x * 256 + threadIdx.x;   // ((b*Tn+t)*C + c)
    int c = idx & 255;
    int t = (int)((idx >> 8) & 4095);
    int b = (int)(idx >> 20);
    float xc = x[b * Tn + t];
    float xp = (t > 0) ? x[b * Tn + t - 1] : 0.f;
    float h = W[c * 2] * xp + W[c * 2 + 1] * xc + bias[c];
    g_hf[idx] = h;
    g_hbf[idx] = __float2half(h);
}

// ---------------- fp16x2-weights mma.sync GEMM kernel ----------------
// mode 0: conv f/g (8 K-chunks, dilation), epilogue gates + col-sum partials.
// mode 1: res 1x1 (4 K-chunks), epilogue residual update.
// grid (Bc*32, 4), 512 threads. CTA: 128 t x 64 out-ch. 16 warps = wm4 x nw4.
// A = single fp16 activations; B = fp16 hi + lo weights (2 MMAs per term).
__global__ void __launch_bounds__(512, 1)
gemm_kernel(int layer, int dil, int mode,
            const float* __restrict__ b0_, const float* __restrict__ b1_) {
    extern __shared__ unsigned char sm[];
    uint32_t smb = smem_u32(sm);
    const int tid = threadIdx.x, wid = tid >> 5, lane = tid & 31;
    const int b = blockIdx.x >> 5, tile = blockIdx.x & 31;
    const int oh2 = blockIdx.y;
    const int t0 = tile * NT;
    const int cg0 = oh2 * 64, oh = oh2 >> 1, slice = oh2 & 1;
    const int nch = mode ? 4 : 8;
    const int nB = mode ? 1024 : 2048;       // B segs: proj 16KB, conv 32KB
    const int nmat = mode ? 1 : 2;
    const int wm = wid & 3, nw = wid >> 2;

    const unsigned char* wbase = mode
        ? g_wp2 + ((size_t)(layer * 2 + oh) << 17)
        : g_wp1 + ((size_t)(layer * 2 + oh) << 19);
    const __half* abf = mode ? g_gbf : g_hbf;

    auto load_chunk = [&](int kc, int s) {
        uint32_t stb = smb + (uint32_t)s * STAGE_BYTES;
        int toff = (!mode && (kc >> 2) == 0) ? dil : 0;
        int c0 = mode ? kc * 64 : (kc & 3) * 64;
        size_t kcs = mode ? ((size_t)kc << 15) : ((size_t)kc << 16);
        int nseg = 1024 + nB;
        #pragma unroll
        for (int it = 0; it < 6; ++it) {
            int idx = it * 512 + tid;
            if (idx < 1024) {                 // A: 128 rows x 128B single fp16
                int r = idx >> 3, j = idx & 7;
                int t = t0 + r - toff;
                int tc = t < 0 ? 0 : t;
                const char* src = (const char*)(abf + ((size_t)b * Tn + tc) * C + c0) + j * 16;
                cp16(stb + swz((uint32_t)(r * 128 + j * 16)), src, t >= 0 ? 16 : 0);
            } else if (idx < nseg) {          // B weights hi/lo, pre-swizzled, linear
                int bi = idx - 1024;
                int ms = bi >> 9, seg = bi & 511;
                const unsigned char* src = wbase + kcs + (size_t)ms * 16384
                                         + (size_t)slice * 8192 + (size_t)seg * 16;
                cp16(stb + 16384 + (uint32_t)bi * 16, src, 16);
            }
        }
        asm volatile("cp.async.commit_group;" ::: "memory");
    };

    load_chunk(0, 0);
    if (nch > 1) load_chunk(1, 1);

    float acc[2][2][2][4];
    #pragma unroll
    for (int m = 0; m < 2; ++m)
        #pragma unroll
        for (int mt = 0; mt < 2; ++mt)
            #pragma unroll
            for (int nt = 0; nt < 2; ++nt)
                #pragma unroll
                for (int q = 0; q < 4; ++q) acc[m][mt][nt][q] = 0.f;

    const int laneA_r = lane & 15, laneA_j = lane >> 4;
    const int laneB_r = ((lane >> 4) << 3) + (lane & 7), laneB_j = (lane >> 3) & 1;

    for (int i = 0; i < nch; ++i) {
        int s = i % NSTAGE;
        if (i + 1 < nch) asm volatile("cp.async.wait_group 1;" ::: "memory");
        else             asm volatile("cp.async.wait_group 0;" ::: "memory");
        __syncthreads();
        if (i + 2 < nch) load_chunk(i + 2, (i + 2) % NSTAGE);

        uint32_t stb = smb + (uint32_t)s * STAGE_BYTES;
        #pragma unroll
        for (int ks = 0; ks < 4; ++ks) {
            uint32_t ah[2][4];
            #pragma unroll
            for (int mt = 0; mt < 2; ++mt) {
                uint32_t off = swz((uint32_t)((wm * 32 + mt * 16 + laneA_r) * 128
                                              + (ks * 2 + laneA_j) * 16));
                LDSM4(ah[mt], stb + off);
            }
            uint32_t offB = swz((uint32_t)((nw * 16 + laneB_r) * 128
                                           + (ks * 2 + laneB_j) * 16));
            #pragma unroll
            for (int m = 0; m < 2; ++m) {
                if (m >= nmat) break;
                uint32_t bB = stb + 16384 + (uint32_t)m * 16384;
                uint32_t bh[4], bl[4];
                LDSM4(bh, bB + offB);
                LDSM4(bl, bB + 8192 + offB);
                #pragma unroll
                for (int mt = 0; mt < 2; ++mt) {
                    MMA(acc[m][mt][0], ah[mt], bh[0], bh[1]);
                    MMA(acc[m][mt][1], ah[mt], bh[2], bh[3]);
                    MMA(acc[m][mt][0], ah[mt], bl[0], bl[1]);
                    MMA(acc[m][mt][1], ah[mt], bl[2], bl[3]);
                }
            }
        }
    }
    __syncthreads();

    const int rbase = t0 + wm * 32 + (lane >> 2);
    const int cbase = cg0 + nw * 16 + (lane & 3) * 2;

    if (mode == 0) {
        float cs[2][2] = {{0.f, 0.f}, {0.f, 0.f}};
        #pragma unroll
        for (int mt = 0; mt < 2; ++mt)
            #pragma unroll
            for (int nt = 0; nt < 2; ++nt) {
                int c = cbase + nt * 8;
                float bf0 = b0_[c], bf1 = b0_[c + 1];
                float bg0 = b1_[c], bg1 = b1_[c + 1];
                #pragma unroll
                for (int hh = 0; hh < 2; ++hh) {
                    int t = rbase + mt * 16 + hh * 8;
                    float f0 = acc[0][mt][nt][2 * hh]     + bf0;
                    float f1 = acc[0][mt][nt][2 * hh + 1] + bf1;
                    float g0 = acc[1][mt][nt][2 * hh]     + bg0;
                    float g1 = acc[1][mt][nt][2 * hh + 1] + bg1;
                    float v0 = tanhf(f0) / (1.f + expf(-g0));
                    float v1 = tanhf(f1) / (1.f + expf(-g1));
                    size_t base = ((size_t)b * Tn + t) * C + c;
                    *(uint32_t*)(g_gbf + base) =
                        pack2(__float2half(v0), __float2half(v1));
                    cs[nt][0] += v0;
                    cs[nt][1] += v1;
                }
            }
        #pragma unroll
        for (int nt = 0; nt < 2; ++nt)
            #pragma unroll
            for (int q = 0; q < 2; ++q) {
                cs[nt][q] += __shfl_down_sync(0xffffffffu, cs[nt][q], 16);
                cs[nt][q] += __shfl_down_sync(0xffffffffu, cs[nt][q], 8);
                cs[nt][q] += __shfl_down_sync(0xffffffffu, cs[nt][q], 4);
            }
        float* psum = (float*)sm;
        if (lane < 4) {
            #pragma unroll
            for (int nt = 0; nt < 2; ++nt) {
                int col = nw * 16 + nt * 8 + lane * 2;
                psum[wm * 64 + col]     = cs[nt][0];
                psum[wm * 64 + col + 1] = cs[nt][1];
            }
        }
        __syncthreads();
        if (tid < 64) {
            float s = psum[tid] + psum[64 + tid] + psum[128 + tid] + psum[192 + tid];
            g_part[(((size_t)layer * Bc + b) * 32 + tile) * C + cg0 + tid] = s;
        }
    } else {
        #pragma unroll
        for (int mt = 0; mt < 2; ++mt)
            #pragma unroll
            for (int nt = 0; nt < 2; ++nt) {
                int c = cbase + nt * 8;
                float br0 = b0_[c], br1 = b0_[c + 1];
                #pragma unroll
                for (int hh = 0; hh < 2; ++hh) {
                    int t = rbase + mt * 16 + hh * 8;
                    size_t base = ((size_t)b * Tn + t) * C + c;
                    float2 hv = *(float2*)(g_hf + base);
                    float n0 = acc[0][mt][nt][2 * hh]     + br0 + hv.x;
                    float n1 = acc[0][mt][nt][2 * hh + 1] + br1 + hv.y;
                    *(float2*)(g_hf + base) = make_float2(n0, n1);
                    *(uint32_t*)(g_hbf + base) =
                        pack2(__float2half(n0), __float2half(n1));
                }
            }
    }
}

// ---------------- pooled tail: tile reduce, then warp-per-channel GEMV ----------------
__global__ void pool_reduce_kernel() {        // grid NENC*Bc, 256 thr
    int lb = blockIdx.x;
    int c = threadIdx.x;
    const float* p = g_part + ((size_t)lb * 32) * C + c;
    float s = 0.f;
    #pragma unroll 8
    for (int t = 0; t < 32; ++t) s += p[(size_t)t * C];
    g_m[lb * C + c] = s;
}
__global__ void pooled_gemv_kernel(const float* __restrict__ Ws, const float* __restrict__ bs) {
    __shared__ float smm[NENC * C];           // 40KB
    int b = blockIdx.x, cg = blockIdx.y;      // grid (Bc, 32)
    int tid = threadIdx.x, w = tid >> 5, lane = tid & 31;
    for (int i = tid; i < NENC * C; i += 256) {
        int l = i >> 8, k = i & 255;
        smm[i] = g_m[(l * Bc + b) * C + k];
    }
    __syncthreads();
    int c = cg * 8 + w;                       // warp per output channel
    float a = 0.f;
    for (int l = 0; l < NENC; ++l) {
        const float* wrow = Ws + ((size_t)l * C + c) * C;
        const float* mrow = smm + l * C;
        #pragma unroll
        for (int k = lane; k < C; k += 32) a += wrow[k] * mrow[k];
    }
    a += __shfl_down_sync(0xffffffffu, a, 16);
    a += __shfl_down_sync(0xffffffffu, a, 8);
    a += __shfl_down_sync(0xffffffffu, a, 4);
    a += __shfl_down_sync(0xffffffffu, a, 2);
    a += __shfl_down_sync(0xffffffffu, a, 1);
    if (lane == 0) {
        float ab = 0.f;
        for (int l = 0; l < NENC; ++l) ab += bs[l * C + c];
        g_pooled[b * C + c] = a * (1.f / Tn) + ab;
    }
}

// ---------------- mu / logvar / reparameterize ----------------
__global__ void fc_kernel(const float* __restrict__ mub, const float* __restrict__ lvb,
                          const float* __restrict__ eps, float* __restrict__ out) {
    int b = blockIdx.x, l = threadIdx.x;
    const float* p = g_pooled + b * C;
    float m0 = mub[l], v0 = lvb[l];
    for (int c = 0; c < C; ++c) {
        float pv = p[c];
        m0 += g_fmuT[c * LATENT + l] * pv;
        v0 += g_flvT[c * LATENT + l] * pv;
    }
    out[4 + b * LATENT + l] = m0;
    out[4 + Bc * LATENT + b * LATENT + l] = v0;
    g_z[b * LATENT + l] = m0 + eps[b * LATENT + l] * expf(0.5f * v0);
}

// ---------------- decoder ----------------
__global__ void dec_kernel(const float* __restrict__ inb,
                           const float* __restrict__ bf, const float* __restrict__ bg,
                           const float* __restrict__ br,
                           const float* __restrict__ outW, const float* __restrict__ outb,
                           float* __restrict__ out) {
    __shared__ float h2[C], fg[C], red[C];
    int b = blockIdx.x, c = threadIdx.x;
    {
        float s = inb[c];
        const float* zz = g_z + b * LATENT;
        #pragma unroll 4
        for (int l = 0; l < LATENT; ++l) s += g_dinT[l * C + c] * zz[l];
        h2[c] = s;
    }
    __syncthreads();
    for (int i = 0; i < NDEC; ++i) {
        float f = bf[i * C + c], g = bg[i * C + c];
        const float* wf = g_dwfT + (size_t)i * C * C;
        const float* wg = g_dwgT + (size_t)i * C * C;
        #pragma unroll 4
        for (int cc = 0; cc < C; ++cc) {
            float h = h2[cc];
            f += wf[cc * C + c] * h;
            g += wg[cc * C + c] * h;
        }
        fg[c] = tanhf(f) / (1.f + expf(-g));
        __syncthreads();
        float r = br[i * C + c];
        const float* wr = g_dwrT + (size_t)i * C * C;
        #pragma unroll 4
        for (int cc = 0; cc < C; ++cc) r += wr[cc * C + c] * fg[cc];
        h2[c] += r;
        __syncthreads();
    }
    red[c] = outW[c] * h2[c];
    __syncthreads();
    for (int off = 128; off; off >>= 1) {
        if (c < off) red[c] += red[c + off];
        __syncthreads();
    }
    if (c == 0) out[b] = red[0] + outb[0];
}

// ---------------- host ----------------
extern "C" void kernel_launch(void* const* d_in, const int* in_sizes, int n_in,
                              void* d_out, int out_size) {
    const float* x        = (const float*)d_in[0];
    const float* eps      = (const float*)d_in[1];
    const float* enc_in_W = (const float*)d_in[2];
    const float* enc_in_b = (const float*)d_in[3];
    const float* enc_Wf   = (const float*)d_in[4];
    const float* enc_bf   = (const float*)d_in[5];
    const float* enc_Wg   = (const float*)d_in[6];
    const float* enc_bg   = (const float*)d_in[7];
    const float* enc_Wr   = (const float*)d_in[8];
    const float* enc_br   = (const float*)d_in[9];
    const float* enc_Ws   = (const float*)d_in[10];
    const float* enc_bs   = (const float*)d_in[11];
    const float* fc_mu_W  = (const float*)d_in[12];
    const float* fc_mu_b  = (const float*)d_in[13];
    const float* fc_lv_W  = (const float*)d_in[14];
    const float* fc_lv_b  = (const float*)d_in[15];
    const float* dec_in_W = (const float*)d_in[16];
    const float* dec_in_b = (const float*)d_in[17];
    const float* dec_Wf   = (const float*)d_in[18];
    const float* dec_bf   = (const float*)d_in[19];
    const float* dec_Wg   = (const float*)d_in[20];
    const float* dec_bg   = (const float*)d_in[21];
    const float* dec_Wr   = (const float*)d_in[22];
    const float* dec_br   = (const float*)d_in[23];
    const float* out_W    = (const float*)d_in[24];
    const float* out_b    = (const float*)d_in[25];
    float* out = (float*)d_out;

    cudaFuncSetAttribute(gemm_kernel, cudaFuncAttributeMaxDynamicSharedMemorySize, SMEM_TOTAL);

    prep1_kernel<<<10240, 256>>>(enc_Wf, enc_Wg);
    prep2_kernel<<<5120, 256>>>(enc_Wr);
    prep3_kernel<<<2560, 256>>>(dec_Wf, dec_Wg, dec_Wr, dec_in_W, fc_mu_W, fc_lv_W);
    enc_in_kernel<<<(Bc * Tn * C) / 256, 256>>>(x, enc_in_W, enc_in_b);

    for (int i = 0; i < NENC; ++i) {
        int dil = 1 << (i % 10);
        gemm_kernel<<<dim3(Bc * 32, 4), 512, SMEM_TOTAL>>>(i, dil, 0,
                                                           enc_bf + i * C, enc_bg + i * C);
        gemm_kernel<<<dim3(Bc * 32, 4), 512, SMEM_TOTAL>>>(i, 0, 1,
                                                           enc_br + i * C, (const float*)0);
    }

    pool_reduce_kernel<<<NENC * Bc, 256>>>();
    pooled_gemv_kernel<<<dim3(Bc, 32), 256>>>(enc_Ws, enc_bs);
    fc_kernel<<<Bc, LATENT>>>(fc_mu_b, fc_lv_b, eps, out);
    dec_kernel<<<Bc, C>>>(dec_in_b, dec_bf, dec_bg, dec_br, out_W, out_b, out);
}

// round 13
// speedup vs baseline: 5.8057x; 1.0856x over previous
#include <cuda_runtime.h>
#include <cuda_fp16.h>
#include <math.h>
#include <stdint.h>

#define Bc 4
#define C 256
#define Tn 4096
#define LATENT 128
#define NENC 40
#define NDEC 10
#define NT 128

#define STAGE_BYTES 81920      // A 16K + B up to 64K
#define SMEM_TOTAL (2 * STAGE_BYTES)

// ---------------- device scratch ----------------
__device__ __align__(16) unsigned char g_wp1[(size_t)NENC * 2 * 8 * 4 * 16384]; // 40MB
__device__ __align__(16) unsigned char g_wp2[(size_t)NENC * 2 * 4 * 2 * 16384]; // 10MB
__device__ __align__(16) float  g_hf  [(size_t)Bc * Tn * C];
__device__ __align__(16) __half g_hbf [(size_t)Bc * Tn * C];
__device__ __align__(16) __half g_gbf [(size_t)Bc * Tn * C];
__device__ float g_part[(size_t)NENC * Bc * 32 * C];
__device__ float g_m[NENC * Bc * C];
__device__ float g_pooled[Bc * C];
__device__ float g_z[Bc * LATENT];
__device__ float g_dwfT[NDEC * C * C], g_dwgT[NDEC * C * C], g_dwrT[NDEC * C * C];
__device__ float g_dinT[LATENT * C];
__device__ float g_fmuT[C * LATENT], g_flvT[C * LATENT];

// ---------------- helpers ----------------
__device__ __forceinline__ uint32_t smem_u32(const void* p) {
    uint32_t a;
    asm("{ .reg .u64 t; cvta.to.shared.u64 t, %1; cvt.u32.u64 %0, t; }" : "=r"(a) : "l"(p));
    return a;
}
__device__ __forceinline__ uint32_t swz(uint32_t off) { return off ^ ((off >> 3) & 0x70); }
__device__ __forceinline__ void cp16(uint32_t dst, const void* src, int sz) {
    asm volatile("cp.async.cg.shared.global [%0], [%1], 16, %2;"
                 :: "r"(dst), "l"(src), "r"(sz) : "memory");
}
#define LDSM4(r, addr) \
    asm volatile("ldmatrix.sync.aligned.m8n8.x4.shared.b16 {%0,%1,%2,%3}, [%4];" \
                 : "=r"((r)[0]), "=r"((r)[1]), "=r"((r)[2]), "=r"((r)[3]) : "r"(addr))
#define MMA(c, a, b0r, b1r) \
    asm volatile("mma.sync.aligned.m16n8k16.row.col.f32.f16.f16.f32 " \
                 "{%0,%1,%2,%3}, {%4,%5,%6,%7}, {%8,%9}, {%0,%1,%2,%3};" \
                 : "+f"((c)[0]), "+f"((c)[1]), "+f"((c)[2]), "+f"((c)[3]) \
                 : "r"((a)[0]), "r"((a)[1]), "r"((a)[2]), "r"((a)[3]), "r"(b0r), "r"(b1r))

__device__ __forceinline__ void split2(float v, __half& h, __half& l) {
    h = __float2half(v);
    l = __float2half(v - __half2float(h));
}
__device__ __forceinline__ uint32_t pack2(__half a, __half b) {
    return (uint32_t)__half_as_ushort(a) | ((uint32_t)__half_as_ushort(b) << 16);
}

// ---------------- weight pre-pack: fp16 hi/lo ----------------
// wp1: [layer][oh][chunk 8][ms 4: f_hi,f_lo,g_hi,g_lo][16384B]
__global__ void prep1_kernel(const float* __restrict__ Wf, const float* __restrict__ Wg) {
    size_t idx = (size_t)blockIdx.x * 256 + threadIdx.x;
    int j2 = idx & 31;
    int r  = (idx >> 5) & 127;
    int kc = (idx >> 12) & 7;
    int oh = (idx >> 15) & 1;
    int l  = (int)(idx >> 16);
    int o = oh * 128 + r;
    int tap = kc >> 2;
    int c = (kc & 3) * 64 + j2 * 2;
    uint32_t boff = swz((uint32_t)(r * 128 + j2 * 4));
    unsigned char* base = g_wp1 + ((((size_t)(l * 2 + oh) * 8 + kc) * 4) << 14) + boff;
    const float* pf = Wf + (((size_t)l * C + o) * C + c) * 2 + tap;
    const float* pg = Wg + (((size_t)l * C + o) * C + c) * 2 + tap;
    __half h0, l0, h1, l1;
    split2(pf[0], h0, l0); split2(pf[2], h1, l1);
    *(uint32_t*)(base)             = pack2(h0, h1);
    *(uint32_t*)(base + 16384)     = pack2(l0, l1);
    split2(pg[0], h0, l0); split2(pg[2], h1, l1);
    *(uint32_t*)(base + 2 * 16384) = pack2(h0, h1);
    *(uint32_t*)(base + 3 * 16384) = pack2(l0, l1);
}
// wp2: [layer][oh][chunk 4][ms 2: r_hi,r_lo][16384B]
__global__ void prep2_kernel(const float* __restrict__ Wr) {
    size_t idx = (size_t)blockIdx.x * 256 + threadIdx.x;
    int j2 = idx & 31;
    int r  = (idx >> 5) & 127;
    int kc = (idx >> 12) & 3;
    int oh = (idx >> 14) & 1;
    int l  = (int)(idx >> 15);
    int o = oh * 128 + r;
    int c = kc * 64 + j2 * 2;
    uint32_t boff = swz((uint32_t)(r * 128 + j2 * 4));
    unsigned char* base = g_wp2 + ((((size_t)(l * 2 + oh) * 4 + kc) * 2) << 14) + boff;
    const float* pr = Wr + ((size_t)l * C + o) * C + c;
    __half h0, l0, h1, l1;
    split2(pr[0], h0, l0); split2(pr[1], h1, l1);
    *(uint32_t*)(base)         = pack2(h0, h1);
    *(uint32_t*)(base + 16384) = pack2(l0, l1);
}
__global__ void prep3_kernel(const float* __restrict__ dWf, const float* __restrict__ dWg,
                             const float* __restrict__ dWr, const float* __restrict__ dinW,
                             const float* __restrict__ muW, const float* __restrict__ lvW) {
    int idx = blockIdx.x * 256 + threadIdx.x;
    if (idx < NDEC * C * C) {
        int o = idx & 255, cc = (idx >> 8) & 255, l = idx >> 16;
        g_dwfT[idx] = dWf[(((size_t)l * C + o) * C + cc) * 2 + 1];
        g_dwgT[idx] = dWg[(((size_t)l * C + o) * C + cc) * 2 + 1];
        g_dwrT[idx] = dWr[((size_t)l * C + o) * C + cc];
    }
    if (idx < LATENT * C) {
        int o = idx & 255, l = idx >> 8;
        g_dinT[idx] = dinW[o * LATENT + l];
    }
    if (idx < C * LATENT) {
        int l = idx & 127, c = idx >> 7;
        g_fmuT[idx] = muW[l * C + c];
        g_flvT[idx] = lvW[l * C + c];
    }
}

// ---------------- encoder input conv ----------------
__global__ void enc_in_kernel(const float* __restrict__ x,
                              const float* __restrict__ W,
                              const float* __restrict__ bias) {
    size_t idx = (size_t)blockIdx.x * 256 + threadIdx.x;
    int c = idx & 255;
    int t = (int)((idx >> 8) & 4095);
    int b = (int)(idx >> 20);
    float xc = x[b * Tn + t];
    float xp = (t > 0) ? x[b * Tn + t - 1] : 0.f;
    float h = W[c * 2] * xp + W[c * 2 + 1] * xc + bias[c];
    g_hf[idx] = h;
    g_hbf[idx] = __float2half(h);
}

// ---------------- fp16x2-weights mma.sync GEMM kernel ----------------
// mode 0: conv f/g (8 K-chunks, dilation). mode 1: res 1x1 (4 K-chunks).
// grid (Bc*32, 2), 512 threads. CTA: 128 t x 128 out-ch. 16 warps = wm4 x nw4,
// per-warp tile 32x32 per matrix. 2-stage pipeline, sync-bracketed prefetch.
__global__ void __launch_bounds__(512, 1)
gemm_kernel(int layer, int dil, int mode,
            const float* __restrict__ b0_, const float* __restrict__ b1_) {
    extern __shared__ unsigned char sm[];
    uint32_t smb = smem_u32(sm);
    const int tid = threadIdx.x, wid = tid >> 5, lane = tid & 31;
    const int b = blockIdx.x >> 5, tile = blockIdx.x & 31;
    const int oh = blockIdx.y;
    const int t0 = tile * NT;
    const int cg0 = oh * 128;
    const int nch = mode ? 4 : 8;
    const int nB = mode ? 2048 : 4096;       // B 16B-segs per chunk
    const int nmat = mode ? 1 : 2;
    const int wm = wid & 3, nw = wid >> 2;

    const unsigned char* wbase = mode
        ? g_wp2 + ((size_t)(layer * 2 + oh) << 17)
        : g_wp1 + ((size_t)(layer * 2 + oh) << 19);
    const __half* abf = mode ? g_gbf : g_hbf;

    auto load_chunk = [&](int kc, int s) {
        uint32_t stb = smb + (uint32_t)s * STAGE_BYTES;
        int toff = (!mode && (kc >> 2) == 0) ? dil : 0;
        int c0 = mode ? kc * 64 : (kc & 3) * 64;
        size_t kcs = mode ? ((size_t)kc << 15) : ((size_t)kc << 16);
        int nseg = 1024 + nB;
        #pragma unroll
        for (int it = 0; it < 10; ++it) {
            int idx = it * 512 + tid;
            if (idx < 1024) {                 // A: 128 rows x 128B single fp16
                int r = idx >> 3, j = idx & 7;
                int t = t0 + r - toff;
                int tc = t < 0 ? 0 : t;
                const char* src = (const char*)(abf + ((size_t)b * Tn + tc) * C + c0) + j * 16;
                cp16(stb + swz((uint32_t)(r * 128 + j * 16)), src, t >= 0 ? 16 : 0);
            } else if (idx < nseg) {          // B weights hi/lo, pre-swizzled, linear
                int bi = idx - 1024;          // ms = bi>>10, full 16KB blocks
                const unsigned char* src = wbase + kcs + (size_t)bi * 16;
                cp16(stb + 16384 + (uint32_t)bi * 16, src, 16);
            }
        }
        asm volatile("cp.async.commit_group;" ::: "memory");
    };

    load_chunk(0, 0);
    load_chunk(1, 1);

    float acc[2][2][4][4];
    #pragma unroll
    for (int m = 0; m < 2; ++m)
        #pragma unroll
        for (int mt = 0; mt < 2; ++mt)
            #pragma unroll
            for (int nt = 0; nt < 4; ++nt)
                #pragma unroll
                for (int q = 0; q < 4; ++q) acc[m][mt][nt][q] = 0.f;

    const int laneA_r = lane & 15, laneA_j = lane >> 4;
    const int laneB_r = ((lane >> 4) << 3) + (lane & 7), laneB_j = (lane >> 3) & 1;

    for (int i = 0; i < nch; ++i) {
        int s = i & 1;
        if (i + 1 < nch) asm volatile("cp.async.wait_group 1;" ::: "memory");
        else             asm volatile("cp.async.wait_group 0;" ::: "memory");
        __syncthreads();

        uint32_t stb = smb + (uint32_t)s * STAGE_BYTES;
        #pragma unroll
        for (int ks = 0; ks < 4; ++ks) {
            uint32_t ah[2][4];
            #pragma unroll
            for (int mt = 0; mt < 2; ++mt) {
                uint32_t off = swz((uint32_t)((wm * 32 + mt * 16 + laneA_r) * 128
                                              + (ks * 2 + laneA_j) * 16));
                LDSM4(ah[mt], stb + off);
            }
            #pragma unroll
            for (int m = 0; m < 2; ++m) {
                if (m >= nmat) break;
                uint32_t bB = stb + 16384 + (uint32_t)m * 32768;
                #pragma unroll
                for (int np = 0; np < 2; ++np) {
                    uint32_t offB = swz((uint32_t)((nw * 32 + np * 16 + laneB_r) * 128
                                                   + (ks * 2 + laneB_j) * 16));
                    uint32_t bh[4], bl[4];
                    LDSM4(bh, bB + offB);
                    LDSM4(bl, bB + 16384 + offB);
                    int n0 = np * 2, n1 = np * 2 + 1;
                    #pragma unroll
                    for (int mt = 0; mt < 2; ++mt) {
                        MMA(acc[m][mt][n0], ah[mt], bh[0], bh[1]);
                        MMA(acc[m][mt][n1], ah[mt], bh[2], bh[3]);
                        MMA(acc[m][mt][n0], ah[mt], bl[0], bl[1]);
                        MMA(acc[m][mt][n1], ah[mt], bl[2], bl[3]);
                    }
                }
            }
        }
        __syncthreads();                      // all reads of stage s done
        if (i + 2 < nch) load_chunk(i + 2, s);
    }

    const int rbase = t0 + wm * 32 + (lane >> 2);
    const int cbase = cg0 + nw * 32 + (lane & 3) * 2;

    if (mode == 0) {
        float cs[4][2] = {{0.f,0.f},{0.f,0.f},{0.f,0.f},{0.f,0.f}};
        #pragma unroll
        for (int mt = 0; mt < 2; ++mt)
            #pragma unroll
            for (int nt = 0; nt < 4; ++nt) {
                int c = cbase + nt * 8;
                float bf0 = b0_[c], bf1 = b0_[c + 1];
                float bg0 = b1_[c], bg1 = b1_[c + 1];
                #pragma unroll
                for (int hh = 0; hh < 2; ++hh) {
                    int t = rbase + mt * 16 + hh * 8;
                    float f0 = acc[0][mt][nt][2 * hh]     + bf0;
                    float f1 = acc[0][mt][nt][2 * hh + 1] + bf1;
                    float g0 = acc[1][mt][nt][2 * hh]     + bg0;
                    float g1 = acc[1][mt][nt][2 * hh + 1] + bg1;
                    float v0 = tanhf(f0) / (1.f + expf(-g0));
                    float v1 = tanhf(f1) / (1.f + expf(-g1));
                    size_t base = ((size_t)b * Tn + t) * C + c;
                    *(uint32_t*)(g_gbf + base) = pack2(__float2half(v0), __float2half(v1));
                    cs[nt][0] += v0;
                    cs[nt][1] += v1;
                }
            }
        #pragma unroll
        for (int nt = 0; nt < 4; ++nt)
            #pragma unroll
            for (int q = 0; q < 2; ++q) {
                cs[nt][q] += __shfl_down_sync(0xffffffffu, cs[nt][q], 16);
                cs[nt][q] += __shfl_down_sync(0xffffffffu, cs[nt][q], 8);
                cs[nt][q] += __shfl_down_sync(0xffffffffu, cs[nt][q], 4);
            }
        float* psum = (float*)sm;             // [4 wm][128 cols]
        if (lane < 4) {
            #pragma unroll
            for (int nt = 0; nt < 4; ++nt) {
                int col = nw * 32 + nt * 8 + lane * 2;
                psum[wm * 128 + col]     = cs[nt][0];
                psum[wm * 128 + col + 1] = cs[nt][1];
            }
        }
        __syncthreads();
        if (tid < 128) {
            float s = psum[tid] + psum[128 + tid] + psum[256 + tid] + psum[384 + tid];
            g_part[(((size_t)layer * Bc + b) * 32 + tile) * C + cg0 + tid] = s;
        }
    } else {
        #pragma unroll
        for (int mt = 0; mt < 2; ++mt)
            #pragma unroll
            for (int nt = 0; nt < 4; ++nt) {
                int c = cbase + nt * 8;
                float br0 = b0_[c], br1 = b0_[c + 1];
                #pragma unroll
                for (int hh = 0; hh < 2; ++hh) {
                    int t = rbase + mt * 16 + hh * 8;
                    size_t base = ((size_t)b * Tn + t) * C + c;
                    float2 hv = *(float2*)(g_hf + base);
                    float n0 = acc[0][mt][nt][2 * hh]     + br0 + hv.x;
                    float n1 = acc[0][mt][nt][2 * hh + 1] + br1 + hv.y;
                    *(float2*)(g_hf + base) = make_float2(n0, n1);
                    *(uint32_t*)(g_hbf + base) = pack2(__float2half(n0), __float2half(n1));
                }
            }
    }
}

// ---------------- pooled tail ----------------
__global__ void pool_reduce_kernel() {        // grid NENC*Bc, 256 thr
    int lb = blockIdx.x;
    int c = threadIdx.x;
    const float* p = g_part + ((size_t)lb * 32) * C + c;
    float s = 0.f;
    #pragma unroll 8
    for (int t = 0; t < 32; ++t) s += p[(size_t)t * C];
    g_m[lb * C + c] = s;
}
__global__ void pooled_gemv_kernel(const float* __restrict__ Ws, const float* __restrict__ bs) {
    __shared__ float smm[NENC * C];
    int b = blockIdx.x, cg = blockIdx.y;      // grid (Bc, 32)
    int tid = threadIdx.x, w = tid >> 5, lane = tid & 31;
    for (int i = tid; i < NENC * C; i += 256) {
        int l = i >> 8, k = i & 255;
        smm[i] = g_m[(l * Bc + b) * C + k];
    }
    __syncthreads();
    int c = cg * 8 + w;
    float a = 0.f;
    for (int l = 0; l < NENC; ++l) {
        const float* wrow = Ws + ((size_t)l * C + c) * C;
        const float* mrow = smm + l * C;
        #pragma unroll
        for (int k = lane; k < C; k += 32) a += wrow[k] * mrow[k];
    }
    a += __shfl_down_sync(0xffffffffu, a, 16);
    a += __shfl_down_sync(0xffffffffu, a, 8);
    a += __shfl_down_sync(0xffffffffu, a, 4);
    a += __shfl_down_sync(0xffffffffu, a, 2);
    a += __shfl_down_sync(0xffffffffu, a, 1);
    if (lane == 0) {
        float ab = 0.f;
        for (int l = 0; l < NENC; ++l) ab += bs[l * C + c];
        g_pooled[b * C + c] = a * (1.f / Tn) + ab;
    }
}

// ---------------- mu / logvar / reparameterize ----------------
__global__ void fc_kernel(const float* __restrict__ mub, const float* __restrict__ lvb,
                          const float* __restrict__ eps, float* __restrict__ out) {
    int b = blockIdx.x, l = threadIdx.x;
    const float* p = g_pooled + b * C;
    float m0 = mub[l], v0 = lvb[l];
    for (int c = 0; c < C; ++c) {
        float pv = p[c];
        m0 += g_fmuT[c * LATENT + l] * pv;
        v0 += g_flvT[c * LATENT + l] * pv;
    }
    out[4 + b * LATENT + l] = m0;
    out[4 + Bc * LATENT + b * LATENT + l] = v0;
    g_z[b * LATENT + l] = m0 + eps[b * LATENT + l] * expf(0.5f * v0);
}

// ---------------- decoder ----------------
__global__ void dec_kernel(const float* __restrict__ inb,
                           const float* __restrict__ bf, const float* __restrict__ bg,
                           const float* __restrict__ br,
                           const float* __restrict__ outW, const float* __restrict__ outb,
                           float* __restrict__ out) {
    __shared__ float h2[C], fg[C], red[C];
    int b = blockIdx.x, c = threadIdx.x;
    {
        float s = inb[c];
        const float* zz = g_z + b * LATENT;
        #pragma unroll 4
        for (int l = 0; l < LATENT; ++l) s += g_dinT[l * C + c] * zz[l];
        h2[c] = s;
    }
    __syncthreads();
    for (int i = 0; i < NDEC; ++i) {
        float f = bf[i * C + c], g = bg[i * C + c];
        const float* wf = g_dwfT + (size_t)i * C * C;
        const float* wg = g_dwgT + (size_t)i * C * C;
        #pragma unroll 4
        for (int cc = 0; cc < C; ++cc) {
            float h = h2[cc];
            f += wf[cc * C + c] * h;
            g += wg[cc * C + c] * h;
        }
        fg[c] = tanhf(f) / (1.f + expf(-g));
        __syncthreads();
        float r = br[i * C + c];
        const float* wr = g_dwrT + (size_t)i * C * C;
        #pragma unroll 4
        for (int cc = 0; cc < C; ++cc) r += wr[cc * C + c] * fg[cc];
        h2[c] += r;
        __syncthreads();
    }
    red[c] = outW[c] * h2[c];
    __syncthreads();
    for (int off = 128; off; off >>= 1) {
        if (c < off) red[c] += red[c + off];
        __syncthreads();
    }
    if (c == 0) out[b] = red[0] + outb[0];
}

// ---------------- host ----------------
extern "C" void kernel_launch(void* const* d_in, const int* in_sizes, int n_in,
                              void* d_out, int out_size) {
    const float* x        = (const float*)d_in[0];
    const float* eps      = (const float*)d_in[1];
    const float* enc_in_W = (const float*)d_in[2];
    const float* enc_in_b = (const float*)d_in[3];
    const float* enc_Wf   = (const float*)d_in[4];
    const float* enc_bf   = (const float*)d_in[5];
    const float* enc_Wg   = (const float*)d_in[6];
    const float* enc_bg   = (const float*)d_in[7];
    const float* enc_Wr   = (const float*)d_in[8];
    const float* enc_br   = (const float*)d_in[9];
    const float* enc_Ws   = (const float*)d_in[10];
    const float* enc_bs   = (const float*)d_in[11];
    const float* fc_mu_W  = (const float*)d_in[12];
    const float* fc_mu_b  = (const float*)d_in[13];
    const float* fc_lv_W  = (const float*)d_in[14];
    const float* fc_lv_b  = (const float*)d_in[15];
    const float* dec_in_W = (const float*)d_in[16];
    const float* dec_in_b = (const float*)d_in[17];
    const float* dec_Wf   = (const float*)d_in[18];
    const float* dec_bf   = (const float*)d_in[19];
    const float* dec_Wg   = (const float*)d_in[20];
    const float* dec_bg   = (const float*)d_in[21];
    const float* dec_Wr   = (const float*)d_in[22];
    const float* dec_br   = (const float*)d_in[23];
    const float* out_W    = (const float*)d_in[24];
    const float* out_b    = (const float*)d_in[25];
    float* out = (float*)d_out;

    cudaFuncSetAttribute(gemm_kernel, cudaFuncAttributeMaxDynamicSharedMemorySize, SMEM_TOTAL);

    prep1_kernel<<<10240, 256>>>(enc_Wf, enc_Wg);
    prep2_kernel<<<5120, 256>>>(enc_Wr);
    prep3_kernel<<<2560, 256>>>(dec_Wf, dec_Wg, dec_Wr, dec_in_W, fc_mu_W, fc_lv_W);
    enc_in_kernel<<<(Bc * Tn * C) / 256, 256>>>(x, enc_in_W, enc_in_b);

    for (int i = 0; i < NENC; ++i) {
        int dil = 1 << (i % 10);
        gemm_kernel<<<dim3(Bc * 32, 2), 512, SMEM_TOTAL>>>(i, dil, 0,
                                                           enc_bf + i * C, enc_bg + i * C);
        gemm_kernel<<<dim3(Bc * 32, 2), 512, SMEM_TOTAL>>>(i, 0, 1,
                                                           enc_br + i * C, (const float*)0);
    }

    pool_reduce_kernel<<<NENC * Bc, 256>>>();
    pooled_gemv_kernel<<<dim3(Bc, 32), 256>>>(enc_Ws, enc_bs);
    fc_kernel<<<Bc, LATENT>>>(fc_mu_b, fc_lv_b, eps, out);
    dec_kernel<<<Bc, C>>>(dec_in_b, dec_bf, dec_bg, dec_br, out_W, out_b, out);
}

// round 14
// speedup vs baseline: 6.0757x; 1.0465x over previous
#include <cuda_runtime.h>
#include <cuda_fp16.h>
#include <math.h>
#include <stdint.h>

#define Bc 4
#define C 256
#define Tn 4096
#define LATENT 128
#define NENC 40
#define NDEC 10
#define NT 128

#define STAGE_BYTES 49152      // A 16K + B up to 32K
#define NSTAGE 2
#define SMEM_TOTAL (NSTAGE * STAGE_BYTES)

// ---------------- device scratch ----------------
__device__ __align__(16) unsigned char g_wp1[(size_t)NENC * 2 * 8 * 4 * 16384]; // 40MB
__device__ __align__(16) unsigned char g_wp2[(size_t)NENC * 2 * 4 * 2 * 16384]; // 10MB
__device__ __align__(16) float  g_hf  [(size_t)Bc * Tn * C];
__device__ __align__(16) __half g_hbf [(size_t)Bc * Tn * C];
__device__ __align__(16) __half g_gbf [(size_t)Bc * Tn * C];
__device__ float g_part[(size_t)NENC * Bc * 32 * C];
__device__ float g_m[NENC * Bc * C];
__device__ float g_pooled[Bc * C];
__device__ float g_z[Bc * LATENT];
__device__ float g_dwfT[NDEC * C * C], g_dwgT[NDEC * C * C], g_dwrT[NDEC * C * C];
__device__ float g_dinT[LATENT * C];
__device__ float g_fmuT[C * LATENT], g_flvT[C * LATENT];

// ---------------- helpers ----------------
__device__ __forceinline__ uint32_t smem_u32(const void* p) {
    uint32_t a;
    asm("{ .reg .u64 t; cvta.to.shared.u64 t, %1; cvt.u32.u64 %0, t; }" : "=r"(a) : "l"(p));
    return a;
}
__device__ __forceinline__ uint32_t swz(uint32_t off) { return off ^ ((off >> 3) & 0x70); }
__device__ __forceinline__ void cp16(uint32_t dst, const void* src, int sz) {
    asm volatile("cp.async.cg.shared.global [%0], [%1], 16, %2;"
                 :: "r"(dst), "l"(src), "r"(sz) : "memory");
}
#define LDSM4(r, addr) \
    asm volatile("ldmatrix.sync.aligned.m8n8.x4.shared.b16 {%0,%1,%2,%3}, [%4];" \
                 : "=r"((r)[0]), "=r"((r)[1]), "=r"((r)[2]), "=r"((r)[3]) : "r"(addr))
#define MMA(c, a, b0r, b1r) \
    asm volatile("mma.sync.aligned.m16n8k16.row.col.f32.f16.f16.f32 " \
                 "{%0,%1,%2,%3}, {%4,%5,%6,%7}, {%8,%9}, {%0,%1,%2,%3};" \
                 : "+f"((c)[0]), "+f"((c)[1]), "+f"((c)[2]), "+f"((c)[3]) \
                 : "r"((a)[0]), "r"((a)[1]), "r"((a)[2]), "r"((a)[3]), "r"(b0r), "r"(b1r))

__device__ __forceinline__ void split2(float v, __half& h, __half& l) {
    h = __float2half(v);
    l = __float2half(v - __half2float(h));
}
__device__ __forceinline__ uint32_t pack2(__half a, __half b) {
    return (uint32_t)__half_as_ushort(a) | ((uint32_t)__half_as_ushort(b) << 16);
}

// ---------------- weight pre-pack: fp16 hi/lo (layouts identical to R12) ----------------
__global__ void prep1_kernel(const float* __restrict__ Wf, const float* __restrict__ Wg) {
    size_t idx = (size_t)blockIdx.x * 256 + threadIdx.x;
    int j2 = idx & 31;
    int r  = (idx >> 5) & 127;
    int kc = (idx >> 12) & 7;
    int oh = (idx >> 15) & 1;
    int l  = (int)(idx >> 16);
    int o = oh * 128 + r;
    int tap = kc >> 2;
    int c = (kc & 3) * 64 + j2 * 2;
    uint32_t boff = swz((uint32_t)(r * 128 + j2 * 4));
    unsigned char* base = g_wp1 + ((((size_t)(l * 2 + oh) * 8 + kc) * 4) << 14) + boff;
    const float* pf = Wf + (((size_t)l * C + o) * C + c) * 2 + tap;
    const float* pg = Wg + (((size_t)l * C + o) * C + c) * 2 + tap;
    __half h0, l0, h1, l1;
    split2(pf[0], h0, l0); split2(pf[2], h1, l1);
    *(uint32_t*)(base)             = pack2(h0, h1);
    *(uint32_t*)(base + 16384)     = pack2(l0, l1);
    split2(pg[0], h0, l0); split2(pg[2], h1, l1);
    *(uint32_t*)(base + 2 * 16384) = pack2(h0, h1);
    *(uint32_t*)(base + 3 * 16384) = pack2(l0, l1);
}
__global__ void prep2_kernel(const float* __restrict__ Wr) {
    size_t idx = (size_t)blockIdx.x * 256 + threadIdx.x;
    int j2 = idx & 31;
    int r  = (idx >> 5) & 127;
    int kc = (idx >> 12) & 3;
    int oh = (idx >> 14) & 1;
    int l  = (int)(idx >> 15);
    int o = oh * 128 + r;
    int c = kc * 64 + j2 * 2;
    uint32_t boff = swz((uint32_t)(r * 128 + j2 * 4));
    unsigned char* base = g_wp2 + ((((size_t)(l * 2 + oh) * 4 + kc) * 2) << 14) + boff;
    const float* pr = Wr + ((size_t)l * C + o) * C + c;
    __half h0, l0, h1, l1;
    split2(pr[0], h0, l0); split2(pr[1], h1, l1);
    *(uint32_t*)(base)         = pack2(h0, h1);
    *(uint32_t*)(base + 16384) = pack2(l0, l1);
}
__global__ void prep3_kernel(const float* __restrict__ dWf, const float* __restrict__ dWg,
                             const float* __restrict__ dWr, const float* __restrict__ dinW,
                             const float* __restrict__ muW, const float* __restrict__ lvW) {
    int idx = blockIdx.x * 256 + threadIdx.x;
    if (idx < NDEC * C * C) {
        int o = idx & 255, cc = (idx >> 8) & 255, l = idx >> 16;
        g_dwfT[idx] = dWf[(((size_t)l * C + o) * C + cc) * 2 + 1];
        g_dwgT[idx] = dWg[(((size_t)l * C + o) * C + cc) * 2 + 1];
        g_dwrT[idx] = dWr[((size_t)l * C + o) * C + cc];
    }
    if (idx < LATENT * C) {
        int o = idx & 255, l = idx >> 8;
        g_dinT[idx] = dinW[o * LATENT + l];
    }
    if (idx < C * LATENT) {
        int l = idx & 127, c = idx >> 7;
        g_fmuT[idx] = muW[l * C + c];
        g_flvT[idx] = lvW[l * C + c];
    }
}

// ---------------- encoder input conv ----------------
__global__ void enc_in_kernel(const float* __restrict__ x,
                              const float* __restrict__ W,
                              const float* __restrict__ bias) {
    size_t idx = (size_t)blockIdx.x * 256 + threadIdx.x;
    int c = idx & 255;
    int t = (int)((idx >> 8) & 4095);
    int b = (int)(idx >> 20);
    float xc = x[b * Tn + t];
    float xp = (t > 0) ? x[b * Tn + t - 1] : 0.f;
    float h = W[c * 2] * xp + W[c * 2 + 1] * xc + bias[c];
    g_hf[idx] = h;
    g_hbf[idx] = __float2half(h);
}

// ---------------- fp16x2-weights mma.sync GEMM kernel, occupancy 2 ----------------
// mode 0: conv f/g (8 K-chunks, dilation). mode 1: res 1x1 (4 K-chunks).
// grid (Bc*32, 4), 256 threads, 2 CTAs/SM. CTA: 128 t x 64 out-ch.
// 8 warps = wm4 x nw2; per-warp tile 32x32 per matrix.
__global__ void __launch_bounds__(256, 2)
gemm_kernel(int layer, int dil, int mode,
            const float* __restrict__ b0_, const float* __restrict__ b1_) {
    extern __shared__ unsigned char sm[];
    uint32_t smb = smem_u32(sm);
    const int tid = threadIdx.x, wid = tid >> 5, lane = tid & 31;
    const int b = blockIdx.x >> 5, tile = blockIdx.x & 31;
    const int oh2 = blockIdx.y;
    const int t0 = tile * NT;
    const int cg0 = oh2 * 64, oh = oh2 >> 1, slice = oh2 & 1;
    const int nch = mode ? 4 : 8;
    const int nB = mode ? 1024 : 2048;
    const int nmat = mode ? 1 : 2;
    const int wm = wid & 3, nw = wid >> 2;

    const unsigned char* wbase = mode
        ? g_wp2 + ((size_t)(layer * 2 + oh) << 17)
        : g_wp1 + ((size_t)(layer * 2 + oh) << 19);
    const __half* abf = mode ? g_gbf : g_hbf;

    auto load_chunk = [&](int kc, int s) {
        uint32_t stb = smb + (uint32_t)s * STAGE_BYTES;
        int toff = (!mode && (kc >> 2) == 0) ? dil : 0;
        int c0 = mode ? kc * 64 : (kc & 3) * 64;
        size_t kcs = mode ? ((size_t)kc << 15) : ((size_t)kc << 16);
        int nseg = 1024 + nB;
        #pragma unroll
        for (int it = 0; it < 12; ++it) {
            int idx = it * 256 + tid;
            if (idx < 1024) {                 // A: 128 rows x 128B single fp16
                int r = idx >> 3, j = idx & 7;
                int t = t0 + r - toff;
                int tc = t < 0 ? 0 : t;
                const char* src = (const char*)(abf + ((size_t)b * Tn + tc) * C + c0) + j * 16;
                cp16(stb + swz((uint32_t)(r * 128 + j * 16)), src, t >= 0 ? 16 : 0);
            } else if (idx < nseg) {          // B weights hi/lo, pre-swizzled, linear
                int bi = idx - 1024;
                int ms = bi >> 9, seg = bi & 511;
                const unsigned char* src = wbase + kcs + (size_t)ms * 16384
                                         + (size_t)slice * 8192 + (size_t)seg * 16;
                cp16(stb + 16384 + (uint32_t)bi * 16, src, 16);
            }
        }
        asm volatile("cp.async.commit_group;" ::: "memory");
    };

    load_chunk(0, 0);
    load_chunk(1, 1);

    float acc[2][2][4][4];
    #pragma unroll
    for (int m = 0; m < 2; ++m)
        #pragma unroll
        for (int mt = 0; mt < 2; ++mt)
            #pragma unroll
            for (int nt = 0; nt < 4; ++nt)
                #pragma unroll
                for (int q = 0; q < 4; ++q) acc[m][mt][nt][q] = 0.f;

    const int laneA_r = lane & 15, laneA_j = lane >> 4;
    const int laneB_r = ((lane >> 4) << 3) + (lane & 7), laneB_j = (lane >> 3) & 1;

    for (int i = 0; i < nch; ++i) {
        int s = i & 1;
        if (i + 1 < nch) asm volatile("cp.async.wait_group 1;" ::: "memory");
        else             asm volatile("cp.async.wait_group 0;" ::: "memory");
        __syncthreads();

        uint32_t stb = smb + (uint32_t)s * STAGE_BYTES;
        #pragma unroll
        for (int ks = 0; ks < 4; ++ks) {
            uint32_t ah[2][4];
            #pragma unroll
            for (int mt = 0; mt < 2; ++mt) {
                uint32_t off = swz((uint32_t)((wm * 32 + mt * 16 + laneA_r) * 128
                                              + (ks * 2 + laneA_j) * 16));
                LDSM4(ah[mt], stb + off);
            }
            #pragma unroll
            for (int m = 0; m < 2; ++m) {
                if (m >= nmat) break;
                uint32_t bB = stb + 16384 + (uint32_t)m * 16384;
                #pragma unroll
                for (int np = 0; np < 2; ++np) {
                    uint32_t offB = swz((uint32_t)((nw * 32 + np * 16 + laneB_r) * 128
                                                   + (ks * 2 + laneB_j) * 16));
                    uint32_t bh[4], bl[4];
                    LDSM4(bh, bB + offB);
                    LDSM4(bl, bB + 8192 + offB);
                    int n0 = np * 2, n1 = np * 2 + 1;
                    #pragma unroll
                    for (int mt = 0; mt < 2; ++mt) {
                        MMA(acc[m][mt][n0], ah[mt], bh[0], bh[1]);
                        MMA(acc[m][mt][n1], ah[mt], bh[2], bh[3]);
                        MMA(acc[m][mt][n0], ah[mt], bl[0], bl[1]);
                        MMA(acc[m][mt][n1], ah[mt], bl[2], bl[3]);
                    }
                }
            }
        }
        __syncthreads();                      // all reads of stage s done
        if (i + 2 < nch) load_chunk(i + 2, s);
    }

    const int rbase = t0 + wm * 32 + (lane >> 2);
    const int cbase = cg0 + nw * 32 + (lane & 3) * 2;

    if (mode == 0) {
        float cs[4][2] = {{0.f,0.f},{0.f,0.f},{0.f,0.f},{0.f,0.f}};
        #pragma unroll
        for (int mt = 0; mt < 2; ++mt)
            #pragma unroll
            for (int nt = 0; nt < 4; ++nt) {
                int c = cbase + nt * 8;
                float bf0 = b0_[c], bf1 = b0_[c + 1];
                float bg0 = b1_[c], bg1 = b1_[c + 1];
                #pragma unroll
                for (int hh = 0; hh < 2; ++hh) {
                    int t = rbase + mt * 16 + hh * 8;
                    float f0 = acc[0][mt][nt][2 * hh]     + bf0;
                    float f1 = acc[0][mt][nt][2 * hh + 1] + bf1;
                    float g0 = acc[1][mt][nt][2 * hh]     + bg0;
                    float g1 = acc[1][mt][nt][2 * hh + 1] + bg1;
                    float v0 = tanhf(f0) / (1.f + expf(-g0));
                    float v1 = tanhf(f1) / (1.f + expf(-g1));
                    size_t base = ((size_t)b * Tn + t) * C + c;
                    *(uint32_t*)(g_gbf + base) = pack2(__float2half(v0), __float2half(v1));
                    cs[nt][0] += v0;
                    cs[nt][1] += v1;
                }
            }
        #pragma unroll
        for (int nt = 0; nt < 4; ++nt)
            #pragma unroll
            for (int q = 0; q < 2; ++q) {
                cs[nt][q] += __shfl_down_sync(0xffffffffu, cs[nt][q], 16);
                cs[nt][q] += __shfl_down_sync(0xffffffffu, cs[nt][q], 8);
                cs[nt][q] += __shfl_down_sync(0xffffffffu, cs[nt][q], 4);
            }
        float* psum = (float*)sm;             // [4 wm][64 cols]
        __syncthreads();
        if (lane < 4) {
            #pragma unroll
            for (int nt = 0; nt < 4; ++nt) {
                int col = nw * 32 + nt * 8 + lane * 2;
                psum[wm * 64 + col]     = cs[nt][0];
                psum[wm * 64 + col + 1] = cs[nt][1];
            }
        }
        __syncthreads();
        if (tid < 64) {
            float s = psum[tid] + psum[64 + tid] + psum[128 + tid] + psum[192 + tid];
            g_part[(((size_t)layer * Bc + b) * 32 + tile) * C + cg0 + tid] = s;
        }
    } else {
        #pragma unroll
        for (int mt = 0; mt < 2; ++mt)
            #pragma unroll
            for (int nt = 0; nt < 4; ++nt) {
                int c = cbase + nt * 8;
                float br0 = b0_[c], br1 = b0_[c + 1];
                #pragma unroll
                for (int hh = 0; hh < 2; ++hh) {
                    int t = rbase + mt * 16 + hh * 8;
                    size_t base = ((size_t)b * Tn + t) * C + c;
                    float2 hv = *(float2*)(g_hf + base);
                    float n0 = acc[0][mt][nt][2 * hh]     + br0 + hv.x;
                    float n1 = acc[0][mt][nt][2 * hh + 1] + br1 + hv.y;
                    *(float2*)(g_hf + base) = make_float2(n0, n1);
                    *(uint32_t*)(g_hbf + base) = pack2(__float2half(n0), __float2half(n1));
                }
            }
    }
}

// ---------------- pooled tail ----------------
__global__ void pool_reduce_kernel() {        // grid NENC*Bc, 256 thr
    int lb = blockIdx.x;
    int c = threadIdx.x;
    const float* p = g_part + ((size_t)lb * 32) * C + c;
    float s = 0.f;
    #pragma unroll 8
    for (int t = 0; t < 32; ++t) s += p[(size_t)t * C];
    g_m[lb * C + c] = s;
}
__global__ void pooled_gemv_kernel(const float* __restrict__ Ws, const float* __restrict__ bs) {
    __shared__ float smm[NENC * C];
    int b = blockIdx.x, cg = blockIdx.y;      // grid (Bc, 32)
    int tid = threadIdx.x, w = tid >> 5, lane = tid & 31;
    for (int i = tid; i < NENC * C; i += 256) {
        int l = i >> 8, k = i & 255;
        smm[i] = g_m[(l * Bc + b) * C + k];
    }
    __syncthreads();
    int c = cg * 8 + w;
    float a = 0.f;
    for (int l = 0; l < NENC; ++l) {
        const float* wrow = Ws + ((size_t)l * C + c) * C;
        const float* mrow = smm + l * C;
        #pragma unroll
        for (int k = lane; k < C; k += 32) a += wrow[k] * mrow[k];
    }
    a += __shfl_down_sync(0xffffffffu, a, 16);
    a += __shfl_down_sync(0xffffffffu, a, 8);
    a += __shfl_down_sync(0xffffffffu, a, 4);
    a += __shfl_down_sync(0xffffffffu, a, 2);
    a += __shfl_down_sync(0xffffffffu, a, 1);
    if (lane == 0) {
        float ab = 0.f;
        for (int l = 0; l < NENC; ++l) ab += bs[l * C + c];
        g_pooled[b * C + c] = a * (1.f / Tn) + ab;
    }
}

// ---------------- mu / logvar / reparameterize ----------------
__global__ void fc_kernel(const float* __restrict__ mub, const float* __restrict__ lvb,
                          const float* __restrict__ eps, float* __restrict__ out) {
    int b = blockIdx.x, l = threadIdx.x;
    const float* p = g_pooled + b * C;
    float m0 = mub[l], v0 = lvb[l];
    for (int c = 0; c < C; ++c) {
        float pv = p[c];
        m0 += g_fmuT[c * LATENT + l] * pv;
        v0 += g_flvT[c * LATENT + l] * pv;
    }
    out[4 + b * LATENT + l] = m0;
    out[4 + Bc * LATENT + b * LATENT + l] = v0;
    g_z[b * LATENT + l] = m0 + eps[b * LATENT + l] * expf(0.5f * v0);
}

// ---------------- decoder ----------------
__global__ void dec_kernel(const float* __restrict__ inb,
                           const float* __restrict__ bf, const float* __restrict__ bg,
                           const float* __restrict__ br,
                           const float* __restrict__ outW, const float* __restrict__ outb,
                           float* __restrict__ out) {
    __shared__ float h2[C], fg[C], red[C];
    int b = blockIdx.x, c = threadIdx.x;
    {
        float s = inb[c];
        const float* zz = g_z + b * LATENT;
        #pragma unroll 4
        for (int l = 0; l < LATENT; ++l) s += g_dinT[l * C + c] * zz[l];
        h2[c] = s;
    }
    __syncthreads();
    for (int i = 0; i < NDEC; ++i) {
        float f = bf[i * C + c], g = bg[i * C + c];
        const float* wf = g_dwfT + (size_t)i * C * C;
        const float* wg = g_dwgT + (size_t)i * C * C;
        #pragma unroll 4
        for (int cc = 0; cc < C; ++cc) {
            float h = h2[cc];
            f += wf[cc * C + c] * h;
            g += wg[cc * C + c] * h;
        }
        fg[c] = tanhf(f) / (1.f + expf(-g));
        __syncthreads();
        float r = br[i * C + c];
        const float* wr = g_dwrT + (size_t)i * C * C;
        #pragma unroll 4
        for (int cc = 0; cc < C; ++cc) r += wr[cc * C + c] * fg[cc];
        h2[c] += r;
        __syncthreads();
    }
    red[c] = outW[c] * h2[c];
    __syncthreads();
    for (int off = 128; off; off >>= 1) {
        if (c < off) red[c] += red[c + off];
        __syncthreads();
    }
    if (c == 0) out[b] = red[0] + outb[0];
}

// ---------------- host ----------------
extern "C" void kernel_launch(void* const* d_in, const int* in_sizes, int n_in,
                              void* d_out, int out_size) {
    const float* x        = (const float*)d_in[0];
    const float* eps      = (const float*)d_in[1];
    const float* enc_in_W = (const float*)d_in[2];
    const float* enc_in_b = (const float*)d_in[3];
    const float* enc_Wf   = (const float*)d_in[4];
    const float* enc_bf   = (const float*)d_in[5];
    const float* enc_Wg   = (const float*)d_in[6];
    const float* enc_bg   = (const float*)d_in[7];
    const float* enc_Wr   = (const float*)d_in[8];
    const float* enc_br   = (const float*)d_in[9];
    const float* enc_Ws   = (const float*)d_in[10];
    const float* enc_bs   = (const float*)d_in[11];
    const float* fc_mu_W  = (const float*)d_in[12];
    const float* fc_mu_b  = (const float*)d_in[13];
    const float* fc_lv_W  = (const float*)d_in[14];
    const float* fc_lv_b  = (const float*)d_in[15];
    const float* dec_in_W = (const float*)d_in[16];
    const float* dec_in_b = (const float*)d_in[17];
    const float* dec_Wf   = (const float*)d_in[18];
    const float* dec_bf   = (const float*)d_in[19];
    const float* dec_Wg   = (const float*)d_in[20];
    const float* dec_bg   = (const float*)d_in[21];
    const float* dec_Wr   = (const float*)d_in[22];
    const float* dec_br   = (const float*)d_in[23];
    const float* out_W    = (const float*)d_in[24];
    const float* out_b    = (const float*)d_in[25];
    float* out = (float*)d_out;

    cudaFuncSetAttribute(gemm_kernel, cudaFuncAttributeMaxDynamicSharedMemorySize, SMEM_TOTAL);

    prep1_kernel<<<10240, 256>>>(enc_Wf, enc_Wg);
    prep2_kernel<<<5120, 256>>>(enc_Wr);
    prep3_kernel<<<2560, 256>>>(dec_Wf, dec_Wg, dec_Wr, dec_in_W, fc_mu_W, fc_lv_W);
    enc_in_kernel<<<(Bc * Tn * C) / 256, 256>>>(x, enc_in_W, enc_in_b);

    for (int i = 0; i < NENC; ++i) {
        int dil = 1 << (i % 10);
        gemm_kernel<<<dim3(Bc * 32, 4), 256, SMEM_TOTAL>>>(i, dil, 0,
                                                           enc_bf + i * C, enc_bg + i * C);
        gemm_kernel<<<dim3(Bc * 32, 4), 256, SMEM_TOTAL>>>(i, 0, 1,
                                                           enc_br + i * C, (const float*)0);
    }

    pool_reduce_kernel<<<NENC * Bc, 256>>>();
    pooled_gemv_kernel<<<dim3(Bc, 32), 256>>>(enc_Ws, enc_bs);
    fc_kernel<<<Bc, LATENT>>>(fc_mu_b, fc_lv_b, eps, out);
    dec_kernel<<<Bc, C>>>(dec_in_b, dec_bf, dec_bg, dec_br, out_W, out_b, out);
}